// round 9
// baseline (speedup 1.0000x reference)
#include <cuda_runtime.h>
#include <cuda_bf16.h>
#include <math.h>
#include <stdint.h>

// ---------------- problem constants ----------------
#define LTOK 8192
#define HDIM 1280
#define MHID 3420
#define MH_P 3424
#define NBLK 4
#define NWIN 128
#define PDIM 1176
#define DMODEL 3584
#define H4 5120
#define LMERG 2048

// K paddings (multiples of 64 for int8 concat halves)
#define KP_P 1216
#define KP_H 1280
#define KP_M 3456
#define KP_4 5120

// ---------------- fp32 scratch ----------------
static constexpr long SZ_LH  = (long)LTOK * HDIM;
static constexpr long SZ_L3H = (long)LTOK * 3 * HDIM;
static constexpr long SZ_LMH = (long)LTOK * MHID;

static constexpr long F_X    = 0;
static constexpr long F_RES  = F_X    + SZ_LH;
static constexpr long F_HB   = F_RES  + SZ_LH;
static constexpr long F_QKV  = F_HB   + SZ_LH;
static constexpr long F_GATE = F_QKV  + SZ_L3H;
static constexpr long F_UP   = F_GATE + SZ_LMH;
static constexpr long F_NRM  = F_UP   + SZ_LMH;
static constexpr long F_ATT  = F_NRM  + SZ_LH;
static constexpr long F_CORR = F_ATT  + SZ_LH;
static constexpr long F_TOTAL = F_CORR + SZ_L3H;
__device__ float g_f32[F_TOTAL];

// ---------------- bf16 scratch (hi parts) ----------------
static constexpr long B_XH  = 0;                                   // [8192][1176]
static constexpr long B_NH  = B_XH  + (long)LTOK * PDIM;           // [8192][1280] / merger [2048][5120]
static constexpr long B_AH  = B_NH  + (long)LTOK * HDIM;           // [8192][1280] / merger [2048][5120]
static constexpr long B_SH  = B_AH  + (long)LTOK * HDIM;           // [8192][3424]
static constexpr long B_PW  = B_SH  + (long)LTOK * MH_P;
static constexpr long B_QW  = B_PW  + (long)PDIM * HDIM;
static constexpr long B_PRW = B_QW  + (long)NBLK * HDIM * 3 * HDIM;
static constexpr long B_GW  = B_PRW + (long)NBLK * HDIM * HDIM;
static constexpr long B_UW  = B_GW  + (long)NBLK * HDIM * MH_P;
static constexpr long B_DW  = B_UW  + (long)NBLK * HDIM * MH_P;
static constexpr long B_M0W = B_DW  + (long)NBLK * MHID * HDIM;
static constexpr long B_M2W = B_M0W + (long)H4 * H4;
static constexpr long B_TOTAL = B_M2W + (long)H4 * DMODEL;
__device__ __nv_bfloat16 g_bf16[B_TOTAL];

// ---------------- int8 scratch (concat hi|lo along K) ----------------
static constexpr long I_XQ  = 0;                                   // [8192][2*1216]
static constexpr long I_NQ  = I_XQ  + (long)LTOK * 2 * KP_P;       // [8192][2560] / merger [2048][10240]
static constexpr long I_AQ  = I_NQ  + (long)LTOK * 2 * KP_H;       // [8192][2560] / merger [2048][10240]
static constexpr long I_SQ  = I_AQ  + (long)LTOK * 2 * KP_H;       // [8192][6912]
static constexpr long I_WP  = I_SQ  + (long)LTOK * 2 * KP_M;       // [1280 n][2432]
static constexpr long I_WQ  = I_WP  + 1280L * 2 * KP_P;            // 4x[3840][2560]
static constexpr long I_WPR = I_WQ  + 4L * 3840 * 2 * KP_H;        // 4x[1280][2560]
static constexpr long I_WG  = I_WPR + 4L * 1280 * 2 * KP_H;        // 4x[3420][2560]
static constexpr long I_WU  = I_WG  + 4L * MHID * 2 * KP_H;
static constexpr long I_WD  = I_WU  + 4L * MHID * 2 * KP_H;        // 4x[1280][6912]
static constexpr long I_WM0 = I_WD  + 4L * 1280 * 2 * KP_M;        // [5120][10240]
static constexpr long I_WM2 = I_WM0 + (long)H4 * 2 * KP_4;         // [3584][10240]
static constexpr long I_TOTAL = I_WM2 + (long)DMODEL * 2 * KP_4;
__device__ int8_t g_i8[I_TOTAL];

// ---------------- scale scratch ----------------
static constexpr long S_X   = 0;
static constexpr long S_N   = S_X  + LTOK;
static constexpr long S_A   = S_N  + LTOK;
static constexpr long S_S   = S_A  + LTOK;
static constexpr long S_WP  = S_S  + LTOK;
static constexpr long S_WQ  = S_WP + HDIM;
static constexpr long S_WPR = S_WQ + 4L * 3840;
static constexpr long S_WG  = S_WPR + 4L * HDIM;
static constexpr long S_WU  = S_WG + 4L * MHID;
static constexpr long S_WD  = S_WU + 4L * MHID;
static constexpr long S_WM0 = S_WD + 4L * HDIM;
static constexpr long S_WM2 = S_WM0 + H4;
static constexpr long S_TOTAL = S_WM2 + DMODEL;
__device__ float g_sc[S_TOTAL];

// ---------------- PTX helpers (base sm_103 target only) ----------------
__device__ __forceinline__ uint32_t smem_to_u32(const void* p) {
    uint32_t a;
    asm("{ .reg .u64 t; cvta.to.shared.u64 t, %1; cvt.u32.u64 %0, t; }" : "=r"(a) : "l"(p));
    return a;
}
__device__ __forceinline__ void cp16(uint32_t dst, const void* src, int bytes) {
    asm volatile("cp.async.cg.shared.global [%0], [%1], 16, %2;"
                 :: "r"(dst), "l"(src), "r"(bytes));
}
#define CP_COMMIT() asm volatile("cp.async.commit_group;" ::: "memory")
#define CP_WAIT2()  asm volatile("cp.async.wait_group 2;" ::: "memory")

__device__ __forceinline__ void ldsm_x4(uint32_t r[4], uint32_t addr) {
    asm volatile("ldmatrix.sync.aligned.m8n8.x4.shared.b16 {%0,%1,%2,%3}, [%4];"
                 : "=r"(r[0]), "=r"(r[1]), "=r"(r[2]), "=r"(r[3]) : "r"(addr));
}
__device__ __forceinline__ void ldsm_x4t(uint32_t r[4], uint32_t addr) {
    asm volatile("ldmatrix.sync.aligned.m8n8.x4.trans.shared.b16 {%0,%1,%2,%3}, [%4];"
                 : "=r"(r[0]), "=r"(r[1]), "=r"(r[2]), "=r"(r[3]) : "r"(addr));
}
__device__ __forceinline__ void mma_bf16(float c[4], const uint32_t a[4],
                                         uint32_t b0, uint32_t b1) {
    asm volatile(
        "mma.sync.aligned.m16n8k16.row.col.f32.bf16.bf16.f32 "
        "{%0,%1,%2,%3}, {%4,%5,%6,%7}, {%8,%9}, {%0,%1,%2,%3};"
        : "+f"(c[0]), "+f"(c[1]), "+f"(c[2]), "+f"(c[3])
        : "r"(a[0]), "r"(a[1]), "r"(a[2]), "r"(a[3]), "r"(b0), "r"(b1));
}
__device__ __forceinline__ void mma_s8(int c[4], uint32_t a0, uint32_t a1,
                                       uint32_t a2, uint32_t a3,
                                       uint32_t b0, uint32_t b1) {
    asm volatile(
        "mma.sync.aligned.m16n8k32.row.col.s32.s8.s8.s32 "
        "{%0,%1,%2,%3}, {%4,%5,%6,%7}, {%8,%9}, {%0,%1,%2,%3};"
        : "+r"(c[0]), "+r"(c[1]), "+r"(c[2]), "+r"(c[3])
        : "r"(a0), "r"(a1), "r"(a2), "r"(a3), "r"(b0), "r"(b1));
}
__device__ __forceinline__ uint32_t lds32(uint32_t addr) {
    uint32_t v;
    asm volatile("ld.shared.b32 %0, [%1];" : "=r"(v) : "r"(addr));
    return v;
}
__device__ __forceinline__ int8_t q8(float v) {
    int x = __float2int_rn(v);
    x = x < -127 ? -127 : (x > 127 ? 127 : x);
    return (int8_t)x;
}

// ---------------- main bf16 GEMM (hi*hi) + corr epilogue ----------------
enum { E_NONE = 0, E_BIAS = 1, E_BIAS_RES = 2, E_BIAS_GELU = 3 };

#define A_STRIDE 40
#define B_STRIDE 136
#define A_TILE_B (128 * A_STRIDE * 2)
#define B_TILE_B (32 * B_STRIDE * 2)
#define STAGE_B  (A_TILE_B + B_TILE_B)       // 18944
#define GEMM_SMEM (3 * STAGE_B)              // 56832
#define GT 256

template<int EPI>
__global__ void __launch_bounds__(GT, 2) tcgemm_kernel(
    const __nv_bfloat16* __restrict__ Ah, const __nv_bfloat16* __restrict__ Bh,
    const float* __restrict__ bias, const float* __restrict__ res,
    const float* __restrict__ corr, float* __restrict__ C,
    int M, int N, int K, int lda, int ldb, int ldc)
{
    extern __shared__ __align__(16) char sm[];
    const uint32_t smem_u = smem_to_u32(sm);
    const int tid = threadIdx.x;
    const int lane = tid & 31, wid = tid >> 5;
    const int wm = wid >> 2, wn = wid & 3;
    const int row0 = blockIdx.y * 128, col0 = blockIdx.x * 128;
    const int nc = (K + 31) / 32;

    auto load_stage = [&](int st, int c) {
        const uint32_t sbase = smem_u + st * STAGE_B;
        const int k0 = c * 32;
        #pragma unroll
        for (int it = 0; it < 2; ++it) {
            int e = tid + it * 256;
            int r = e >> 2, q = e & 3;
            int gr = row0 + r, gk = k0 + q * 8;
            int bytes = (K - gk) * 2;
            bytes = bytes < 0 ? 0 : (bytes > 16 ? 16 : bytes);
            const __nv_bfloat16* g = Ah + (long)gr * lda + (bytes > 0 ? gk : 0);
            cp16(sbase + r * (A_STRIDE * 2) + q * 16, g, bytes);
        }
        #pragma unroll
        for (int it = 0; it < 2; ++it) {
            int e = tid + it * 256;
            int r = e >> 4, q = e & 15;
            int gk = k0 + r, gc = col0 + q * 8;
            int bytes = (N - gc) * 2;
            bytes = bytes < 0 ? 0 : (bytes > 16 ? 16 : bytes);
            if (gk >= K) bytes = 0;
            const __nv_bfloat16* g = Bh + (long)(gk < K ? gk : 0) * ldb + (bytes > 0 ? gc : 0);
            cp16(sbase + A_TILE_B + r * (B_STRIDE * 2) + q * 16, g, bytes);
        }
    };

    const int a_row = lane & 15;
    const int a_kh = (lane >> 4) * 8;
    const int b_g = lane >> 3, b_l = lane & 7;
    const int b_k = (b_g & 1) * 8 + b_l;
    const int b_n = (b_g >> 1) * 8;

    float acc[4][4][4];
    #pragma unroll
    for (int i = 0; i < 4; ++i)
        #pragma unroll
        for (int j = 0; j < 4; ++j)
            #pragma unroll
            for (int r = 0; r < 4; ++r) acc[i][j][r] = 0.f;

    #pragma unroll
    for (int s = 0; s < 3; ++s) { if (s < nc) load_stage(s, s); CP_COMMIT(); }

    for (int c = 0; c < nc; ++c) {
        CP_WAIT2();
        __syncthreads();
        const int st = c % 3;
        const uint32_t aB = smem_u + st * STAGE_B;
        const uint32_t bB = aB + A_TILE_B;
        #pragma unroll
        for (int ks = 0; ks < 2; ++ks) {
            uint32_t af[4][4];
            #pragma unroll
            for (int i = 0; i < 4; ++i)
                ldsm_x4(af[i], aB + 2u * ((wm * 64 + i * 16 + a_row) * A_STRIDE + ks * 16 + a_kh));
            #pragma unroll
            for (int j2 = 0; j2 < 2; ++j2) {
                uint32_t bf[4];
                ldsm_x4t(bf, bB + 2u * ((ks * 16 + b_k) * B_STRIDE + wn * 32 + j2 * 16 + b_n));
                #pragma unroll
                for (int i = 0; i < 4; ++i) {
                    mma_bf16(acc[i][2 * j2],     af[i], bf[0], bf[1]);
                    mma_bf16(acc[i][2 * j2 + 1], af[i], bf[2], bf[3]);
                }
            }
        }
        __syncthreads();
        if (c + 3 < nc) load_stage(st, c + 3);
        CP_COMMIT();
    }

    const int g = lane >> 2, t = lane & 3;
    #pragma unroll
    for (int i = 0; i < 4; ++i) {
        #pragma unroll
        for (int j = 0; j < 4; ++j) {
            int col = col0 + wn * 32 + j * 8 + t * 2;
            if (col >= N) continue;
            float b0 = 0.f, b1 = 0.f;
            if (EPI != E_NONE) { b0 = bias[col]; b1 = bias[col + 1]; }
            #pragma unroll
            for (int rr = 0; rr < 2; ++rr) {
                int row = row0 + wm * 64 + i * 16 + g + rr * 8;
                if (row >= M) continue;
                long idx = (long)row * ldc + col;
                float v0 = acc[i][j][rr * 2 + 0] + b0 + corr[idx];
                float v1 = acc[i][j][rr * 2 + 1] + b1 + corr[idx + 1];
                if (EPI == E_BIAS_RES) { v0 += res[idx]; v1 += res[idx + 1]; }
                if (EPI == E_BIAS_GELU) {
                    v0 = 0.5f * v0 * (1.f + erff(v0 * 0.70710678118654752f));
                    v1 = 0.5f * v1 * (1.f + erff(v1 * 0.70710678118654752f));
                }
                *reinterpret_cast<float2*>(C + idx) = make_float2(v0, v1);
            }
        }
    }
}

// ---------------- int8 correction GEMM over concatenated K' ----------------
#define IA_STRIDE 80
#define I_TILE_B (128 * IA_STRIDE)          // 10240
#define I_STAGE_B (2 * I_TILE_B)            // 20480
#define I_GEMM_SMEM (3 * I_STAGE_B)         // 61440

__global__ void __launch_bounds__(GT, 2) i8gemm_kernel(
    const int8_t* __restrict__ qA, int ldqa,
    const int8_t* __restrict__ qB, int ldqb,
    const float* __restrict__ sa, const float* __restrict__ sb,
    float* __restrict__ corr, int M, int N, int K2, int ldc)
{
    extern __shared__ __align__(16) char sm[];
    const uint32_t smem_u = smem_to_u32(sm);
    const int tid = threadIdx.x;
    const int lane = tid & 31, wid = tid >> 5;
    const int wm = wid >> 2, wn = wid & 3;
    const int row0 = blockIdx.y * 128, col0 = blockIdx.x * 128;
    const int nc = K2 / 64;

    auto load_stage = [&](int st, int c) {
        const uint32_t sbase = smem_u + st * I_STAGE_B;
        const int k0 = c * 64;
        #pragma unroll
        for (int it = 0; it < 2; ++it) {
            int e = tid + it * 256;
            int r = e >> 2, q = e & 3;
            int gr = row0 + r;
            const int8_t* g = qA + (long)gr * ldqa + k0 + q * 16;
            cp16(sbase + r * IA_STRIDE + q * 16, g, 16);
        }
        #pragma unroll
        for (int it = 0; it < 2; ++it) {
            int e = tid + it * 256;
            int r = e >> 2, q = e & 3;
            int gn = col0 + r;
            int bytes = (gn < N) ? 16 : 0;
            const int8_t* g = qB + (long)(gn < N ? gn : 0) * ldqb + k0 + q * 16;
            cp16(sbase + I_TILE_B + r * IA_STRIDE + q * 16, g, bytes);
        }
    };

    const int g = lane >> 2, lm = (lane & 3) * 4;

    int acc[4][4][4];
    #pragma unroll
    for (int i = 0; i < 4; ++i)
        #pragma unroll
        for (int j = 0; j < 4; ++j)
            #pragma unroll
            for (int r = 0; r < 4; ++r) acc[i][j][r] = 0;

    #pragma unroll
    for (int s = 0; s < 3; ++s) { if (s < nc) load_stage(s, s); CP_COMMIT(); }

    for (int c = 0; c < nc; ++c) {
        CP_WAIT2();
        __syncthreads();
        const int st = c % 3;
        const uint32_t aB = smem_u + st * I_STAGE_B;
        const uint32_t bB = aB + I_TILE_B;
        #pragma unroll
        for (int ks = 0; ks < 2; ++ks) {
            const uint32_t kbase = ks * 32 + lm;
            uint32_t a0[4], a1[4], a2[4], a3[4];
            #pragma unroll
            for (int i = 0; i < 4; ++i) {
                uint32_t base = aB + (wm * 64 + i * 16 + g) * IA_STRIDE + kbase;
                a0[i] = lds32(base);
                a1[i] = lds32(base + 8 * IA_STRIDE);
                a2[i] = lds32(base + 16);
                a3[i] = lds32(base + 8 * IA_STRIDE + 16);
            }
            #pragma unroll
            for (int nt = 0; nt < 4; ++nt) {
                uint32_t bbase = bB + (wn * 32 + nt * 8 + g) * IA_STRIDE + kbase;
                uint32_t b0 = lds32(bbase);
                uint32_t b1 = lds32(bbase + 16);
                #pragma unroll
                for (int i = 0; i < 4; ++i)
                    mma_s8(acc[i][nt], a0[i], a1[i], a2[i], a3[i], b0, b1);
            }
        }
        __syncthreads();
        if (c + 3 < nc) load_stage(st, c + 3);
        CP_COMMIT();
    }

    const float INV = 1.f / (127.f * 127.f * 256.f);
    const int t = lane & 3;
    #pragma unroll
    for (int i = 0; i < 4; ++i) {
        #pragma unroll
        for (int j = 0; j < 4; ++j) {
            int col = col0 + wn * 32 + j * 8 + t * 2;
            if (col >= N) continue;
            float sb0 = sb[col] * INV, sb1 = sb[col + 1] * INV;
            #pragma unroll
            for (int rr = 0; rr < 2; ++rr) {
                int row = row0 + wm * 64 + i * 16 + g + rr * 8;
                if (row >= M) continue;
                float s = sa[row];
                long idx = (long)row * ldc + col;
                *reinterpret_cast<float2*>(corr + idx) = make_float2(
                    s * sb0 * (float)acc[i][j][rr * 2 + 0],
                    s * sb1 * (float)acc[i][j][rr * 2 + 1]);
            }
        }
    }
}

// ---------------- fused windowed attention with inline RoPE (fp32 out) ----------------
#define SP 81
#define ATTN_SMEM ((3 * 64 * SP + 64 * 64) * 4)

__global__ void __launch_bounds__(256) attn_kernel(
    const float* __restrict__ qkv, const float* __restrict__ cosb,
    const float* __restrict__ sinb, float* __restrict__ out)
{
    extern __shared__ float smf[];
    float* q = smf;
    float* k = smf + 64 * SP;
    float* v = smf + 2 * 64 * SP;
    float* s = smf + 3 * 64 * SP;

    const int w = blockIdx.x >> 4;
    const int h = blockIdx.x & 15;
    const int tid = threadIdx.x;
    const float scale = 0.11180339887498949f;

    for (int e = tid; e < 64 * 80; e += 256) {
        int t = e / 80, j = e % 80;
        int l = w * 64 + t;
        long base = (long)l * (3 * HDIM) + h * 80;
        float c = cosb[l * 80 + j], sn = sinb[l * 80 + j];
        float qv = qkv[base + j];
        float qr = (j < 40) ? -qkv[base + j + 40] : qkv[base + j - 40];
        q[t * SP + j] = qv * c + qr * sn;
        float kv = qkv[base + HDIM + j];
        float kr = (j < 40) ? -qkv[base + HDIM + j + 40] : qkv[base + HDIM + j - 40];
        k[t * SP + j] = kv * c + kr * sn;
        v[t * SP + j] = qkv[base + 2 * HDIM + j];
    }
    __syncthreads();

    {
        const int tx = tid & 15, ty = tid >> 4;
        float acc[4][4] = {};
        for (int d = 0; d < 80; d++) {
            float qa[4], kb[4];
            #pragma unroll
            for (int i = 0; i < 4; i++) qa[i] = q[(ty * 4 + i) * SP + d];
            #pragma unroll
            for (int j = 0; j < 4; j++) kb[j] = k[(tx * 4 + j) * SP + d];
            #pragma unroll
            for (int i = 0; i < 4; i++)
                #pragma unroll
                for (int j = 0; j < 4; j++)
                    acc[i][j] += qa[i] * kb[j];
        }
        #pragma unroll
        for (int i = 0; i < 4; i++)
            #pragma unroll
            for (int j = 0; j < 4; j++)
                s[(ty * 4 + i) * 64 + tx * 4 + j] = acc[i][j] * scale;
    }
    __syncthreads();

    {
        const int warp = tid >> 5, lane = tid & 31;
        for (int r = warp; r < 64; r += 8) {
            float x0 = s[r * 64 + lane], x1 = s[r * 64 + 32 + lane];
            float mx = fmaxf(x0, x1);
            #pragma unroll
            for (int o = 16; o > 0; o >>= 1) mx = fmaxf(mx, __shfl_xor_sync(~0u, mx, o));
            float e0 = __expf(x0 - mx), e1 = __expf(x1 - mx);
            float sum = e0 + e1;
            #pragma unroll
            for (int o = 16; o > 0; o >>= 1) sum += __shfl_xor_sync(~0u, sum, o);
            float inv = 1.f / sum;
            s[r * 64 + lane] = e0 * inv;
            s[r * 64 + 32 + lane] = e1 * inv;
        }
    }
    __syncthreads();

    {
        const int tx = tid & 15, ty = tid >> 4;
        float acc[4][5] = {};
        for (int kk = 0; kk < 64; kk++) {
            float sa[4], vb[5];
            #pragma unroll
            for (int i = 0; i < 4; i++) sa[i] = s[(ty * 4 + i) * 64 + kk];
            #pragma unroll
            for (int j = 0; j < 5; j++) vb[j] = v[kk * SP + tx * 5 + j];
            #pragma unroll
            for (int i = 0; i < 4; i++)
                #pragma unroll
                for (int j = 0; j < 5; j++)
                    acc[i][j] += sa[i] * vb[j];
        }
        #pragma unroll
        for (int i = 0; i < 4; i++) {
            long obase = (long)(w * 64 + ty * 4 + i) * HDIM + h * 80 + tx * 5;
            #pragma unroll
            for (int j = 0; j < 5; j++) out[obase + j] = acc[i][j];
        }
    }
}

// ---------------- generic row quantizer ----------------
// src [rows][K] fp32 -> hi bf16 [rows][ldh] (cols<KH; zero pad K..KH),
// q int8 [rows][2*KP] = [qh | ql*256], per-row scale sc.
__global__ void __launch_bounds__(256) quant_rows_kernel(
    const float* __restrict__ src, int K, int KP, int KH,
    __nv_bfloat16* __restrict__ hi, int ldh,
    int8_t* __restrict__ q, float* __restrict__ sc)
{
    __shared__ float buf[5120];
    __shared__ float red[8];
    __shared__ float s_inv, s_val;
    const int row = blockIdx.x, tid = threadIdx.x;
    const long base = (long)row * K;
    float m = 0.f;
    for (int k = tid * 4; k < K; k += 1024) {
        float4 v = *reinterpret_cast<const float4*>(src + base + k);
        buf[k] = v.x; buf[k + 1] = v.y; buf[k + 2] = v.z; buf[k + 3] = v.w;
        m = fmaxf(m, fmaxf(fmaxf(fabsf(v.x), fabsf(v.y)), fmaxf(fabsf(v.z), fabsf(v.w))));
    }
    #pragma unroll
    for (int o = 16; o > 0; o >>= 1) m = fmaxf(m, __shfl_xor_sync(~0u, m, o));
    if ((tid & 31) == 0) red[tid >> 5] = m;
    __syncthreads();
    if (tid == 0) {
        float t = 0.f;
        #pragma unroll
        for (int i = 0; i < 8; i++) t = fmaxf(t, red[i]);
        t = fmaxf(t, 1e-30f);
        s_val = t; s_inv = 127.f / t;
    }
    __syncthreads();
    const float inv = s_inv;
    const long hbase = (long)row * ldh;
    const long qbase = (long)row * (2 * KP);
    for (int k = tid * 4; k < KP; k += 1024) {
        __nv_bfloat16 h4[4]; char qh[4], ql[4];
        #pragma unroll
        for (int j = 0; j < 4; j++) {
            float v = (k + j < K) ? buf[k + j] : 0.f;
            __nv_bfloat16 hb = __float2bfloat16(v);
            float hf = __bfloat162float(hb);
            h4[j] = hb;
            qh[j] = q8(hf * inv);
            ql[j] = q8((v - hf) * inv * 256.f);
        }
        if (k < KH) *reinterpret_cast<uint2*>(hi + hbase + k) = *reinterpret_cast<uint2*>(h4);
        *reinterpret_cast<char4*>(q + qbase + k)      = *reinterpret_cast<char4*>(qh);
        *reinterpret_cast<char4*>(q + qbase + KP + k) = *reinterpret_cast<char4*>(ql);
    }
    if (tid == 0) sc[row] = s_val;
}

// ---------------- fused (add)+RMSNorm; quantized out OR fp32 out ----------------
__global__ void __launch_bounds__(256) rmsnormq_kernel(
    const float* __restrict__ a, const float* __restrict__ b,
    const float* __restrict__ w, float* __restrict__ sum_out,
    float* __restrict__ f32_out,
    __nv_bfloat16* __restrict__ hi, int8_t* __restrict__ q, float* __restrict__ sc)
{
    __shared__ float sv[HDIM];
    __shared__ float red[8];
    __shared__ float s_scale, s_inv, s_val;
    const int row = blockIdx.x, tid = threadIdx.x;
    const long base = (long)row * HDIM;
    float ss = 0.f;
    for (int j = tid; j < HDIM; j += 256) {
        float v = a[base + j];
        if (b) v += b[base + j];
        sv[j] = v;
        if (sum_out) sum_out[base + j] = v;
        ss += v * v;
    }
    #pragma unroll
    for (int o = 16; o > 0; o >>= 1) ss += __shfl_xor_sync(~0u, ss, o);
    if ((tid & 31) == 0) red[tid >> 5] = ss;
    __syncthreads();
    if (tid == 0) {
        float t = 0.f;
        #pragma unroll
        for (int i = 0; i < 8; i++) t += red[i];
        s_scale = rsqrtf(t / (float)HDIM + 1e-6f);
    }
    __syncthreads();
    float scl = s_scale;
    // normalized values back into sv + max
    float m = 0.f;
    for (int j = tid; j < HDIM; j += 256) {
        float v = sv[j] * scl * w[j];
        sv[j] = v;
        m = fmaxf(m, fabsf(v));
    }
    if (f32_out) {
        __syncthreads();
        for (int j = tid; j < HDIM; j += 256) f32_out[base + j] = sv[j];
        return;
    }
    #pragma unroll
    for (int o = 16; o > 0; o >>= 1) m = fmaxf(m, __shfl_xor_sync(~0u, m, o));
    __syncthreads();
    if ((tid & 31) == 0) red[tid >> 5] = m;
    __syncthreads();
    if (tid == 0) {
        float t = 0.f;
        #pragma unroll
        for (int i = 0; i < 8; i++) t = fmaxf(t, red[i]);
        t = fmaxf(t, 1e-30f);
        s_val = t; s_inv = 127.f / t;
    }
    __syncthreads();
    const float inv = s_inv;
    const long qbase = (long)row * (2 * KP_H);
    for (int k = tid * 4; k < HDIM; k += 1024) {
        __nv_bfloat16 h4[4]; char qh[4], ql[4];
        #pragma unroll
        for (int j = 0; j < 4; j++) {
            float v = sv[k + j];
            __nv_bfloat16 hb = __float2bfloat16(v);
            float hf = __bfloat162float(hb);
            h4[j] = hb;
            qh[j] = q8(hf * inv);
            ql[j] = q8((v - hf) * inv * 256.f);
        }
        *reinterpret_cast<uint2*>(hi + base + k) = *reinterpret_cast<uint2*>(h4);
        *reinterpret_cast<char4*>(q + qbase + k)         = *reinterpret_cast<char4*>(qh);
        *reinterpret_cast<char4*>(q + qbase + KP_H + k)  = *reinterpret_cast<char4*>(ql);
    }
    if (tid == 0) sc[row] = s_val;
}

// ---------------- fused SwiGLU + quantize (row = 3420) ----------------
__global__ void __launch_bounds__(256) swigluq_kernel(
    const float* __restrict__ gte, const float* __restrict__ u,
    __nv_bfloat16* __restrict__ hi, int8_t* __restrict__ q, float* __restrict__ sc)
{
    __shared__ float buf[MHID];
    __shared__ float red[8];
    __shared__ float s_inv, s_val;
    const int row = blockIdx.x, tid = threadIdx.x;
    const long base = (long)row * MHID;
    float m = 0.f;
    for (int k = tid * 4; k < MHID; k += 1024) {
        float4 gv = *reinterpret_cast<const float4*>(gte + base + k);
        float4 uv = *reinterpret_cast<const float4*>(u + base + k);
        float r[4] = {gv.x, gv.y, gv.z, gv.w};
        float s[4] = {uv.x, uv.y, uv.z, uv.w};
        #pragma unroll
        for (int j = 0; j < 4; j++) {
            float x = r[j];
            float v = x / (1.f + __expf(-x)) * s[j];
            buf[k + j] = v;
            m = fmaxf(m, fabsf(v));
        }
    }
    #pragma unroll
    for (int o = 16; o > 0; o >>= 1) m = fmaxf(m, __shfl_xor_sync(~0u, m, o));
    if ((tid & 31) == 0) red[tid >> 5] = m;
    __syncthreads();
    if (tid == 0) {
        float t = 0.f;
        #pragma unroll
        for (int i = 0; i < 8; i++) t = fmaxf(t, red[i]);
        t = fmaxf(t, 1e-30f);
        s_val = t; s_inv = 127.f / t;
    }
    __syncthreads();
    const float inv = s_inv;
    const long hbase = (long)row * MH_P;
    const long qbase = (long)row * (2 * KP_M);
    for (int k = tid * 4; k < KP_M; k += 1024) {
        __nv_bfloat16 h4[4]; char qh[4], ql[4];
        #pragma unroll
        for (int j = 0; j < 4; j++) {
            float v = (k + j < MHID) ? buf[k + j] : 0.f;
            __nv_bfloat16 hb = __float2bfloat16(v);
            float hf = __bfloat162float(hb);
            h4[j] = hb;
            qh[j] = q8(hf * inv);
            ql[j] = q8((v - hf) * inv * 256.f);
        }
        if (k < MH_P) *reinterpret_cast<uint2*>(hi + hbase + k) = *reinterpret_cast<uint2*>(h4);
        *reinterpret_cast<char4*>(q + qbase + k)        = *reinterpret_cast<char4*>(qh);
        *reinterpret_cast<char4*>(q + qbase + KP_M + k) = *reinterpret_cast<char4*>(ql);
    }
    if (tid == 0) sc[row] = s_val;
}

// ---------------- weight prep: hi split, col max, transpose-quant ----------------
__global__ void __launch_bounds__(256) splitH_kernel(
    const float* __restrict__ in, __nv_bfloat16* __restrict__ out,
    long rows, int cols, int ldo)
{
    int c4n = cols >> 2;
    long total = rows * c4n;
    for (long i = (long)blockIdx.x * 256 + threadIdx.x; i < total; i += (long)gridDim.x * 256) {
        long r = i / c4n;
        int c4 = (int)(i - r * c4n);
        float4 v = *reinterpret_cast<const float4*>(in + r * cols + c4 * 4);
        __nv_bfloat16 h4[4] = { __float2bfloat16(v.x), __float2bfloat16(v.y),
                                __float2bfloat16(v.z), __float2bfloat16(v.w) };
        *reinterpret_cast<uint2*>(out + r * ldo + c4 * 4) = *reinterpret_cast<uint2*>(h4);
    }
}

__global__ void __launch_bounds__(256) colmax_kernel(
    const float* __restrict__ B, float* __restrict__ sb, int K, int N)
{
    int n = blockIdx.x * 256 + threadIdx.x;
    if (n >= N) return;
    float m = 0.f;
    for (int k = 0; k < K; ++k) m = fmaxf(m, fabsf(B[(long)k * N + n]));
    sb[n] = fmaxf(m, 1e-30f);
}

// B [K][N] -> q [N][2*KP] : half0 = ql*256, half1 = qh (pairs with A = [qh|ql])
__global__ void __launch_bounds__(256) wquant_kernel(
    const float* __restrict__ B, const float* __restrict__ sb,
    int8_t* __restrict__ q, int K, int N, int KP, int ldq)
{
    __shared__ int8_t sl[64][68];
    __shared__ int8_t sh[64][68];
    const int k0 = blockIdx.x * 64, n0 = blockIdx.y * 64;
    const int tid = threadIdx.x;
    for (int idx = tid; idx < 4096; idx += 256) {
        int kl = idx >> 6, nl = idx & 63;
        int gk = k0 + kl, gn = n0 + nl;
        float v = (gk < K && gn < N) ? B[(long)gk * N + gn] : 0.f;
        float s = (gn < N) ? sb[gn] : 1.f;
        float inv = 127.f / s;
        __nv_bfloat16 hb = __float2bfloat16(v);
        float hf = __bfloat162float(hb);
        sh[nl][kl] = q8(hf * inv);
        sl[nl][kl] = q8((v - hf) * inv * 256.f);
    }
    __syncthreads();
    for (int idx = tid; idx < 1024; idx += 256) {
        int nl = idx >> 4, kq = (idx & 15) * 4;
        int gn = n0 + nl;
        if (gn >= N) continue;
        long base = (long)gn * ldq + k0 + kq;
        char4 cl = make_char4(sl[nl][kq], sl[nl][kq + 1], sl[nl][kq + 2], sl[nl][kq + 3]);
        char4 ch = make_char4(sh[nl][kq], sh[nl][kq + 1], sh[nl][kq + 2], sh[nl][kq + 3]);
        *reinterpret_cast<char4*>(q + base)      = cl;
        *reinterpret_cast<char4*>(q + base + KP) = ch;
    }
}

// ---------------- host ----------------
static inline dim3 ggrid(int M, int N) { return dim3((N + 127) / 128, (M + 127) / 128); }

extern "C" void kernel_launch(void* const* d_in, const int* in_sizes, int n_in,
                              void* d_out, int out_size)
{
    const float* x       = (const float*)d_in[0];
    const float* cosb    = (const float*)d_in[1];
    const float* sinb    = (const float*)d_in[2];
    const float* patch_w = (const float*)d_in[3];
    const float* norm1_w = (const float*)d_in[4];
    const float* norm2_w = (const float*)d_in[5];
    const float* qkv_w   = (const float*)d_in[6];
    const float* qkv_b   = (const float*)d_in[7];
    const float* proj_w  = (const float*)d_in[8];
    const float* proj_b  = (const float*)d_in[9];
    const float* gate_w  = (const float*)d_in[10];
    const float* gate_b  = (const float*)d_in[11];
    const float* up_w    = (const float*)d_in[12];
    const float* up_b    = (const float*)d_in[13];
    const float* down_w  = (const float*)d_in[14];
    const float* down_b  = (const float*)d_in[15];
    const float* lnq_w   = (const float*)d_in[16];
    const float* m0_w    = (const float*)d_in[17];
    const float* m0_b    = (const float*)d_in[18];
    const float* m2_w    = (const float*)d_in[19];
    const float* m2_b    = (const float*)d_in[20];

    float* fs = nullptr; __nv_bfloat16* bh = nullptr; int8_t* qi = nullptr; float* sc = nullptr;
    cudaGetSymbolAddress((void**)&fs, g_f32);
    cudaGetSymbolAddress((void**)&bh, g_bf16);
    cudaGetSymbolAddress((void**)&qi, g_i8);
    cudaGetSymbolAddress((void**)&sc, g_sc);

    float *pX = fs+F_X, *pRES = fs+F_RES, *pHB = fs+F_HB, *pQKV = fs+F_QKV;
    float *pGATE = fs+F_GATE, *pUP = fs+F_UP, *pNRM = fs+F_NRM, *pATT = fs+F_ATT, *pCORR = fs+F_CORR;

    __nv_bfloat16 *xH = bh+B_XH, *nH = bh+B_NH, *aH = bh+B_AH, *sH = bh+B_SH;
    __nv_bfloat16 *pwH = bh+B_PW, *qwH = bh+B_QW, *prH = bh+B_PRW, *gwH = bh+B_GW;
    __nv_bfloat16 *uwH = bh+B_UW, *dwH = bh+B_DW, *m0H = bh+B_M0W, *m2H = bh+B_M2W;

    int8_t *xQ = qi+I_XQ, *nQ = qi+I_NQ, *aQ = qi+I_AQ, *sQ = qi+I_SQ;
    int8_t *wpQ = qi+I_WP, *wqQ = qi+I_WQ, *wprQ = qi+I_WPR, *wgQ = qi+I_WG;
    int8_t *wuQ = qi+I_WU, *wdQ = qi+I_WD, *wm0Q = qi+I_WM0, *wm2Q = qi+I_WM2;

    float *sX = sc+S_X, *sN = sc+S_N, *sA = sc+S_A, *sS = sc+S_S;
    float *sWP = sc+S_WP, *sWQ = sc+S_WQ, *sWPR = sc+S_WPR, *sWG = sc+S_WG;
    float *sWU = sc+S_WU, *sWD = sc+S_WD, *sWM0 = sc+S_WM0, *sWM2 = sc+S_WM2;

    cudaFuncSetAttribute(tcgemm_kernel<E_NONE>, cudaFuncAttributeMaxDynamicSharedMemorySize, GEMM_SMEM);
    cudaFuncSetAttribute(tcgemm_kernel<E_BIAS>, cudaFuncAttributeMaxDynamicSharedMemorySize, GEMM_SMEM);
    cudaFuncSetAttribute(tcgemm_kernel<E_BIAS_RES>, cudaFuncAttributeMaxDynamicSharedMemorySize, GEMM_SMEM);
    cudaFuncSetAttribute(tcgemm_kernel<E_BIAS_GELU>, cudaFuncAttributeMaxDynamicSharedMemorySize, GEMM_SMEM);
    cudaFuncSetAttribute(i8gemm_kernel, cudaFuncAttributeMaxDynamicSharedMemorySize, I_GEMM_SMEM);
    cudaFuncSetAttribute(attn_kernel, cudaFuncAttributeMaxDynamicSharedMemorySize, ATTN_SMEM);

    auto prepw = [&](const float* w, __nv_bfloat16* hi, int ldh, int8_t* q, float* sbv,
                     int K, int KP, int N) {
        long t4 = (long)K * (N / 4);
        int blks = (int)((t4 + 255) / 256); if (blks > 16384) blks = 16384;
        splitH_kernel<<<blks, 256>>>(w, hi, K, N, ldh);
        colmax_kernel<<<(N + 255) / 256, 256>>>(w, sbv, K, N);
        dim3 g2((KP + 63) / 64, (N + 63) / 64);
        wquant_kernel<<<g2, 256>>>(w, sbv, q, K, N, KP, 2 * KP);
    };

    // ---- weight + input prep ----
    prepw(patch_w, pwH, HDIM, wpQ, sWP, PDIM, KP_P, HDIM);
    for (int d = 0; d < NBLK; d++) {
        prepw(qkv_w  + (long)d*HDIM*3*HDIM, qwH + (long)d*HDIM*3*HDIM, 3*HDIM,
              wqQ  + (long)d*3840*2*KP_H, sWQ  + (long)d*3840, HDIM, KP_H, 3*HDIM);
        prepw(proj_w + (long)d*HDIM*HDIM,  prH + (long)d*HDIM*HDIM,  HDIM,
              wprQ + (long)d*HDIM*2*KP_H, sWPR + (long)d*HDIM, HDIM, KP_H, HDIM);
        prepw(gate_w + (long)d*HDIM*MHID,  gwH + (long)d*HDIM*MH_P,  MH_P,
              wgQ  + (long)d*MHID*2*KP_H, sWG  + (long)d*MHID, HDIM, KP_H, MHID);
        prepw(up_w   + (long)d*HDIM*MHID,  uwH + (long)d*HDIM*MH_P,  MH_P,
              wuQ  + (long)d*MHID*2*KP_H, sWU  + (long)d*MHID, HDIM, KP_H, MHID);
        prepw(down_w + (long)d*MHID*HDIM,  dwH + (long)d*MHID*HDIM,  HDIM,
              wdQ  + (long)d*HDIM*2*KP_M, sWD  + (long)d*HDIM, MHID, KP_M, HDIM);
    }
    prepw(m0_w, m0H, H4,     wm0Q, sWM0, H4, KP_4, H4);
    prepw(m2_w, m2H, DMODEL, wm2Q, sWM2, H4, KP_4, DMODEL);

    quant_rows_kernel<<<LTOK, 256>>>(x, PDIM, KP_P, PDIM, xH, PDIM, xQ, sX);
    cudaMemsetAsync(pRES, 0, SZ_LH * sizeof(float));

    // ---- patch embed ----
    i8gemm_kernel<<<ggrid(LTOK, HDIM), GT, I_GEMM_SMEM>>>(
        xQ, 2*KP_P, wpQ, 2*KP_P, sX, sWP, pCORR, LTOK, HDIM, 2*KP_P, HDIM);
    tcgemm_kernel<E_NONE><<<ggrid(LTOK, HDIM), GT, GEMM_SMEM>>>(
        xH, pwH, nullptr, nullptr, pCORR, pX, LTOK, HDIM, PDIM, PDIM, HDIM, HDIM);

    for (int d = 0; d < NBLK; d++) {
        // norm1 (fused quant) ; hb = x+res
        rmsnormq_kernel<<<LTOK, 256>>>(pX, pRES, norm1_w + (long)d*HDIM, pHB, nullptr, nH, nQ, sN);
        // qkv
        i8gemm_kernel<<<ggrid(LTOK, 3*HDIM), GT, I_GEMM_SMEM>>>(
            nQ, 2*KP_H, wqQ + (long)d*3840*2*KP_H, 2*KP_H, sN, sWQ + (long)d*3840,
            pCORR, LTOK, 3*HDIM, 2*KP_H, 3*HDIM);
        tcgemm_kernel<E_BIAS><<<ggrid(LTOK, 3*HDIM), GT, GEMM_SMEM>>>(
            nH, qwH + (long)d*HDIM*3*HDIM, qkv_b + (long)d*3*HDIM, nullptr, pCORR, pQKV,
            LTOK, 3*HDIM, HDIM, HDIM, 3*HDIM, 3*HDIM);
        // attention (fp32) + quant
        attn_kernel<<<NWIN * 16, 256, ATTN_SMEM>>>(pQKV, cosb, sinb, pATT);
        quant_rows_kernel<<<LTOK, 256>>>(pATT, HDIM, KP_H, HDIM, aH, HDIM, aQ, sA);
        // proj + residual
        i8gemm_kernel<<<ggrid(LTOK, HDIM), GT, I_GEMM_SMEM>>>(
            aQ, 2*KP_H, wprQ + (long)d*HDIM*2*KP_H, 2*KP_H, sA, sWPR + (long)d*HDIM,
            pCORR, LTOK, HDIM, 2*KP_H, HDIM);
        tcgemm_kernel<E_BIAS_RES><<<ggrid(LTOK, HDIM), GT, GEMM_SMEM>>>(
            aH, prH + (long)d*HDIM*HDIM, proj_b + (long)d*HDIM, pHB, pCORR, pRES,
            LTOK, HDIM, HDIM, HDIM, HDIM, HDIM);
        // norm2
        rmsnormq_kernel<<<LTOK, 256>>>(pRES, nullptr, norm2_w + (long)d*HDIM, nullptr, nullptr, nH, nQ, sN);
        // gate
        i8gemm_kernel<<<ggrid(LTOK, MHID), GT, I_GEMM_SMEM>>>(
            nQ, 2*KP_H, wgQ + (long)d*MHID*2*KP_H, 2*KP_H, sN, sWG + (long)d*MHID,
            pCORR, LTOK, MHID, 2*KP_H, MHID);
        tcgemm_kernel<E_BIAS><<<ggrid(LTOK, MHID), GT, GEMM_SMEM>>>(
            nH, gwH + (long)d*HDIM*MH_P, gate_b + (long)d*MHID, nullptr, pCORR, pGATE,
            LTOK, MHID, HDIM, HDIM, MH_P, MHID);
        // up
        i8gemm_kernel<<<ggrid(LTOK, MHID), GT, I_GEMM_SMEM>>>(
            nQ, 2*KP_H, wuQ + (long)d*MHID*2*KP_H, 2*KP_H, sN, sWU + (long)d*MHID,
            pCORR, LTOK, MHID, 2*KP_H, MHID);
        tcgemm_kernel<E_BIAS><<<ggrid(LTOK, MHID), GT, GEMM_SMEM>>>(
            nH, uwH + (long)d*HDIM*MH_P, up_b + (long)d*MHID, nullptr, pCORR, pUP,
            LTOK, MHID, HDIM, HDIM, MH_P, MHID);
        // swiglu (fused quant)
        swigluq_kernel<<<LTOK, 256>>>(pGATE, pUP, sH, sQ, sS);
        // down
        i8gemm_kernel<<<ggrid(LTOK, HDIM), GT, I_GEMM_SMEM>>>(
            sQ, 2*KP_M, wdQ + (long)d*HDIM*2*KP_M, 2*KP_M, sS, sWD + (long)d*HDIM,
            pCORR, LTOK, HDIM, 2*KP_M, HDIM);
        tcgemm_kernel<E_BIAS><<<ggrid(LTOK, HDIM), GT, GEMM_SMEM>>>(
            sH, dwH + (long)d*MHID*HDIM, down_b + (long)d*HDIM, nullptr, pCORR, pX,
            LTOK, HDIM, MHID, MH_P, HDIM, HDIM);
    }

    // ---- merger ----
    rmsnormq_kernel<<<LTOK, 256>>>(pX, pRES, lnq_w, nullptr, pNRM, nullptr, nullptr, nullptr);
    quant_rows_kernel<<<LMERG, 256>>>(pNRM, H4, KP_4, H4, nH, H4, nQ, sN);
    i8gemm_kernel<<<ggrid(LMERG, H4), GT, I_GEMM_SMEM>>>(
        nQ, 2*KP_4, wm0Q, 2*KP_4, sN, sWM0, pCORR, LMERG, H4, 2*KP_4, H4);
    tcgemm_kernel<E_BIAS_GELU><<<ggrid(LMERG, H4), GT, GEMM_SMEM>>>(
        nH, m0H, m0_b, nullptr, pCORR, pATT, LMERG, H4, H4, H4, H4, H4);
    quant_rows_kernel<<<LMERG, 256>>>(pATT, H4, KP_4, H4, aH, H4, aQ, sA);
    i8gemm_kernel<<<ggrid(LMERG, DMODEL), GT, I_GEMM_SMEM>>>(
        aQ, 2*KP_4, wm2Q, 2*KP_4, sA, sWM2, pCORR, LMERG, DMODEL, 2*KP_4, DMODEL);
    tcgemm_kernel<E_BIAS><<<ggrid(LMERG, DMODEL), GT, GEMM_SMEM>>>(
        aH, m2H, m2_b, nullptr, pCORR, (float*)d_out, LMERG, DMODEL, H4, H4, DMODEL, DMODEL);
}

// round 10
// speedup vs baseline: 2.1978x; 2.1978x over previous
#include <cuda_runtime.h>
#include <cuda_bf16.h>
#include <math.h>
#include <stdint.h>

// ---------------- problem constants ----------------
#define LTOK 8192
#define HDIM 1280
#define NHEAD 16
#define HEADD 80
#define MHID 3420
#define MH_P 3424          // padded leading dim (16B-aligned bf16 rows)
#define NBLK 4
#define NWIN 128
#define PDIM 1176
#define DMODEL 3584
#define H4 5120
#define LMERG 2048

// ---------------- fp32 scratch ----------------
static constexpr long SZ_LH  = (long)LTOK * HDIM;
static constexpr long SZ_L3H = (long)LTOK * 3 * HDIM;
static constexpr long SZ_LMH = (long)LTOK * MHID;

static constexpr long F_X    = 0;
static constexpr long F_RES  = F_X   + SZ_LH;
static constexpr long F_HB   = F_RES + SZ_LH;
static constexpr long F_QKV  = F_HB  + SZ_LH;
static constexpr long F_GATE = F_QKV + SZ_L3H;
static constexpr long F_UP   = F_GATE + SZ_LMH;
static constexpr long F_TOTAL = F_UP + SZ_LMH;
__device__ float g_f32[F_TOTAL];

// ---------------- bf16 scratch (hi/lo pairs) ----------------
static constexpr long SZ_XS  = (long)LTOK * PDIM;
static constexpr long SZ_PW  = (long)PDIM * HDIM;
static constexpr long SZ_QW  = (long)NBLK * HDIM * 3*HDIM;
static constexpr long SZ_PRW = (long)NBLK * HDIM * HDIM;
static constexpr long SZ_GWP = (long)NBLK * HDIM * MH_P;   // padded
static constexpr long SZ_DW  = (long)NBLK * MHID * HDIM;
static constexpr long SZ_M0W = (long)H4 * H4;
static constexpr long SZ_M2W = (long)H4 * DMODEL;
static constexpr long SZ_SHP = (long)LTOK * MH_P;          // padded swiglu out

static constexpr long B_XH  = 0;
static constexpr long B_XL  = B_XH + SZ_XS;
static constexpr long B_NH  = B_XL + SZ_XS;
static constexpr long B_NL  = B_NH + SZ_LH;
static constexpr long B_AH  = B_NL + SZ_LH;
static constexpr long B_AL  = B_AH + SZ_LH;
static constexpr long B_SH  = B_AL + SZ_LH;
static constexpr long B_SL  = B_SH + SZ_SHP;
static constexpr long B_PW  = B_SL + SZ_SHP;
static constexpr long B_QW  = B_PW + 2*SZ_PW;
static constexpr long B_PRW = B_QW + 2*SZ_QW;
static constexpr long B_GW  = B_PRW + 2*SZ_PRW;
static constexpr long B_UW  = B_GW + 2*SZ_GWP;
static constexpr long B_DW  = B_UW + 2*SZ_GWP;
static constexpr long B_M0W = B_DW + 2*SZ_DW;
static constexpr long B_M2W = B_M0W + 2*SZ_M0W;
static constexpr long B_TOTAL = B_M2W + 2*SZ_M2W;
__device__ __nv_bfloat16 g_bf16[B_TOTAL];

// ---------------- PTX helpers (base sm_103 target only!) ----------------
__device__ __forceinline__ uint32_t smem_to_u32(const void* p) {
    uint32_t a;
    asm("{ .reg .u64 t; cvta.to.shared.u64 t, %1; cvt.u32.u64 %0, t; }" : "=r"(a) : "l"(p));
    return a;
}
__device__ __forceinline__ void cp16(uint32_t dst, const void* src, int bytes) {
    asm volatile("cp.async.cg.shared.global [%0], [%1], 16, %2;"
                 :: "r"(dst), "l"(src), "r"(bytes));
}
#define CP_COMMIT() asm volatile("cp.async.commit_group;" ::: "memory")
#define CP_WAIT2()  asm volatile("cp.async.wait_group 2;" ::: "memory")

__device__ __forceinline__ void ldsm_x4(uint32_t r[4], uint32_t addr) {
    asm volatile("ldmatrix.sync.aligned.m8n8.x4.shared.b16 {%0,%1,%2,%3}, [%4];"
                 : "=r"(r[0]), "=r"(r[1]), "=r"(r[2]), "=r"(r[3]) : "r"(addr));
}
__device__ __forceinline__ void ldsm_x4t(uint32_t r[4], uint32_t addr) {
    asm volatile("ldmatrix.sync.aligned.m8n8.x4.trans.shared.b16 {%0,%1,%2,%3}, [%4];"
                 : "=r"(r[0]), "=r"(r[1]), "=r"(r[2]), "=r"(r[3]) : "r"(addr));
}
__device__ __forceinline__ void mma_bf16(float c[4], const uint32_t a[4],
                                         uint32_t b0, uint32_t b1) {
    asm volatile(
        "mma.sync.aligned.m16n8k16.row.col.f32.bf16.bf16.f32 "
        "{%0,%1,%2,%3}, {%4,%5,%6,%7}, {%8,%9}, {%0,%1,%2,%3};"
        : "+f"(c[0]), "+f"(c[1]), "+f"(c[2]), "+f"(c[3])
        : "r"(a[0]), "r"(a[1]), "r"(a[2]), "r"(a[3]), "r"(b0), "r"(b1));
}

// ---------------- tensor-core GEMM (bf16x3 split, fp32 accum) ----------------
enum { E_NONE = 0, E_BIAS = 1, E_BIAS_RES = 2, E_GELU_SPLIT = 3 };

// Tiles: BM=128, BN=128, BK=32. 8 warps in 2(M)x4(N); warp tile 64x32.
// Launch bounds (256, 2): cap regs at 128 so 2 CTAs co-reside per SM.
#define A_STRIDE 40
#define B_STRIDE 136
#define A_TILE_B (128 * A_STRIDE * 2)      // 10240
#define B_TILE_B (32 * B_STRIDE * 2)       // 8704
#define STAGE_B  (2 * A_TILE_B + 2 * B_TILE_B)  // 37888
#define OFF_AH 0
#define OFF_AL A_TILE_B
#define OFF_BH (2 * A_TILE_B)
#define OFF_BL (2 * A_TILE_B + B_TILE_B)
#define GEMM_SMEM (3 * STAGE_B)            // 113664
#define GT 256

template<int EPI>
__global__ void __launch_bounds__(GT, 2) tcgemm_kernel(
    const __nv_bfloat16* __restrict__ Ah, const __nv_bfloat16* __restrict__ Al,
    const __nv_bfloat16* __restrict__ Bh, const __nv_bfloat16* __restrict__ Bl,
    const float* __restrict__ bias, const float* __restrict__ res,
    float* __restrict__ C, __nv_bfloat16* __restrict__ Oh, __nv_bfloat16* __restrict__ Ol,
    int M, int N, int K, int lda, int ldb, int ldc)
{
    extern __shared__ __align__(16) char sm[];
    const uint32_t smem_u = smem_to_u32(sm);
    const int tid = threadIdx.x;
    const int lane = tid & 31, wid = tid >> 5;
    const int wm = wid >> 2, wn = wid & 3;        // 2(M) x 4(N) warp grid
    const int row0 = blockIdx.y * 128, col0 = blockIdx.x * 128;

    const int nc = (K + 31) / 32;

    auto load_stage = [&](int st, int c) {
        const uint32_t sbase = smem_u + st * STAGE_B;
        const int k0 = c * 32;
        #pragma unroll
        for (int h = 0; h < 2; ++h) {
            const __nv_bfloat16* src = h ? Al : Ah;
            const uint32_t dbase = sbase + (h ? OFF_AL : OFF_AH);
            #pragma unroll
            for (int it = 0; it < 2; ++it) {
                int e = tid + it * 256;
                int r = e >> 2, q = e & 3;
                int gr = row0 + r;
                int gk = k0 + q * 8;
                int bytes = (K - gk) * 2;
                bytes = bytes < 0 ? 0 : (bytes > 16 ? 16 : bytes);
                const __nv_bfloat16* g = src + (long)gr * lda + (bytes > 0 ? gk : 0);
                cp16(dbase + r * (A_STRIDE * 2) + q * 16, g, bytes);
            }
        }
        #pragma unroll
        for (int h = 0; h < 2; ++h) {
            const __nv_bfloat16* src = h ? Bl : Bh;
            const uint32_t dbase = sbase + (h ? OFF_BL : OFF_BH);
            #pragma unroll
            for (int it = 0; it < 2; ++it) {
                int e = tid + it * 256;
                int r = e >> 4, q = e & 15;
                int gk = k0 + r;
                int gc = col0 + q * 8;
                int bytes = (N - gc) * 2;
                bytes = bytes < 0 ? 0 : (bytes > 16 ? 16 : bytes);
                if (gk >= K) bytes = 0;
                const __nv_bfloat16* g = src + (long)(gk < K ? gk : 0) * ldb + (bytes > 0 ? gc : 0);
                cp16(dbase + r * (B_STRIDE * 2) + q * 16, g, bytes);
            }
        }
    };

    const int a_row = lane & 15;
    const int a_kh = (lane >> 4) * 8;
    const int b_g = lane >> 3, b_l = lane & 7;
    const int b_k = (b_g & 1) * 8 + b_l;
    const int b_n = (b_g >> 1) * 8;

    float acc[4][4][4];
    #pragma unroll
    for (int i = 0; i < 4; ++i)
        #pragma unroll
        for (int j = 0; j < 4; ++j)
            #pragma unroll
            for (int r = 0; r < 4; ++r) acc[i][j][r] = 0.f;

    #pragma unroll
    for (int s = 0; s < 3; ++s) {
        if (s < nc) load_stage(s, s);
        CP_COMMIT();
    }

    for (int c = 0; c < nc; ++c) {
        CP_WAIT2();
        __syncthreads();
        const int st = c % 3;
        const uint32_t sbase = smem_u + st * STAGE_B;
        const uint32_t aB[2] = { sbase + OFF_AH, sbase + OFF_AL };
        const uint32_t bB[2] = { sbase + OFF_BH, sbase + OFF_BL };

        #pragma unroll
        for (int ks = 0; ks < 2; ++ks) {
            uint32_t af[2][4][4];
            #pragma unroll
            for (int h = 0; h < 2; ++h)
                #pragma unroll
                for (int i = 0; i < 4; ++i)
                    ldsm_x4(af[h][i],
                        aB[h] + 2u * ((wm * 64 + i * 16 + a_row) * A_STRIDE + ks * 16 + a_kh));
            #pragma unroll
            for (int j2 = 0; j2 < 2; ++j2) {
                uint32_t b0[4], b1[4];
                uint32_t boff = 2u * ((ks * 16 + b_k) * B_STRIDE + wn * 32 + j2 * 16 + b_n);
                ldsm_x4t(b0, bB[0] + boff);
                ldsm_x4t(b1, bB[1] + boff);
                #pragma unroll
                for (int i = 0; i < 4; ++i) {
                    mma_bf16(acc[i][2*j2],   af[0][i], b0[0], b0[1]);
                    mma_bf16(acc[i][2*j2+1], af[0][i], b0[2], b0[3]);
                    mma_bf16(acc[i][2*j2],   af[0][i], b1[0], b1[1]);
                    mma_bf16(acc[i][2*j2+1], af[0][i], b1[2], b1[3]);
                    mma_bf16(acc[i][2*j2],   af[1][i], b0[0], b0[1]);
                    mma_bf16(acc[i][2*j2+1], af[1][i], b0[2], b0[3]);
                }
            }
        }
        __syncthreads();
        if (c + 3 < nc) load_stage(st, c + 3);
        CP_COMMIT();
    }

    const int g = lane >> 2, t = lane & 3;
    #pragma unroll
    for (int i = 0; i < 4; ++i) {
        #pragma unroll
        for (int j = 0; j < 4; ++j) {
            int col = col0 + wn * 32 + j * 8 + t * 2;
            if (col >= N) continue;
            float b0 = 0.f, b1 = 0.f;
            if (EPI != E_NONE) { b0 = bias[col]; b1 = bias[col + 1]; }
            #pragma unroll
            for (int rr = 0; rr < 2; ++rr) {
                int row = row0 + wm * 64 + i * 16 + g + rr * 8;
                if (row >= M) continue;
                float v0 = acc[i][j][rr * 2 + 0] + b0;
                float v1 = acc[i][j][rr * 2 + 1] + b1;
                long idx = (long)row * ldc + col;
                if (EPI == E_BIAS_RES) { v0 += res[idx]; v1 += res[idx + 1]; }
                if (EPI == E_GELU_SPLIT) {
                    v0 = 0.5f * v0 * (1.f + erff(v0 * 0.70710678118654752f));
                    v1 = 0.5f * v1 * (1.f + erff(v1 * 0.70710678118654752f));
                    __nv_bfloat16 h0 = __float2bfloat16(v0);
                    __nv_bfloat16 h1 = __float2bfloat16(v1);
                    Oh[idx] = h0; Oh[idx + 1] = h1;
                    Ol[idx]     = __float2bfloat16(v0 - __bfloat162float(h0));
                    Ol[idx + 1] = __float2bfloat16(v1 - __bfloat162float(h1));
                } else {
                    float2 o = make_float2(v0, v1);
                    *reinterpret_cast<float2*>(C + idx) = o;
                }
            }
        }
    }
}

// ---------------- fused windowed attention with inline RoPE (fp32) ----------------
// Score buffer aliases q's smem (q is dead after the QK phase): smem drops
// 78.3KB -> 62.2KB so 3 CTAs/SM co-reside on this latency-bound kernel.
#define SP 81
#define ATTN_SMEM (3 * 64 * SP * 4)

__global__ void __launch_bounds__(256) attn_kernel(
    const float* __restrict__ qkv, const float* __restrict__ cosb,
    const float* __restrict__ sinb, __nv_bfloat16* __restrict__ outH,
    __nv_bfloat16* __restrict__ outL)
{
    extern __shared__ float smf[];
    float* q = smf;
    float* k = smf + 64 * SP;
    float* v = smf + 2 * 64 * SP;
    float* s = smf;                 // aliases q (dead after QK phase)

    const int w = blockIdx.x >> 4;
    const int h = blockIdx.x & 15;
    const int tid = threadIdx.x;
    const float scale = 0.11180339887498949f;

    for (int e = tid; e < 64 * 80; e += 256) {
        int t = e / 80, j = e % 80;
        int l = w * 64 + t;
        long base = (long)l * (3 * HDIM) + h * 80;
        float c = cosb[l * 80 + j], sn = sinb[l * 80 + j];
        float qv = qkv[base + j];
        float qr = (j < 40) ? -qkv[base + j + 40] : qkv[base + j - 40];
        q[t * SP + j] = qv * c + qr * sn;
        float kv = qkv[base + HDIM + j];
        float kr = (j < 40) ? -qkv[base + HDIM + j + 40] : qkv[base + HDIM + j - 40];
        k[t * SP + j] = kv * c + kr * sn;
        v[t * SP + j] = qkv[base + 2 * HDIM + j];
    }
    __syncthreads();

    {
        const int tx = tid & 15, ty = tid >> 4;
        float acc[4][4] = {};
        for (int d = 0; d < 80; d++) {
            float qa[4], kb[4];
            #pragma unroll
            for (int i = 0; i < 4; i++) qa[i] = q[(ty * 4 + i) * SP + d];
            #pragma unroll
            for (int j = 0; j < 4; j++) kb[j] = k[(tx * 4 + j) * SP + d];
            #pragma unroll
            for (int i = 0; i < 4; i++)
                #pragma unroll
                for (int j = 0; j < 4; j++)
                    acc[i][j] += qa[i] * kb[j];
        }
        __syncthreads();   // all reads of q complete before s overwrites it
        #pragma unroll
        for (int i = 0; i < 4; i++)
            #pragma unroll
            for (int j = 0; j < 4; j++)
                s[(ty * 4 + i) * 64 + tx * 4 + j] = acc[i][j] * scale;
    }
    __syncthreads();

    {
        const int warp = tid >> 5, lane = tid & 31;
        for (int r = warp; r < 64; r += 8) {
            float x0 = s[r * 64 + lane], x1 = s[r * 64 + 32 + lane];
            float mx = fmaxf(x0, x1);
            #pragma unroll
            for (int o = 16; o > 0; o >>= 1) mx = fmaxf(mx, __shfl_xor_sync(~0u, mx, o));
            float e0 = __expf(x0 - mx), e1 = __expf(x1 - mx);
            float sum = e0 + e1;
            #pragma unroll
            for (int o = 16; o > 0; o >>= 1) sum += __shfl_xor_sync(~0u, sum, o);
            float inv = 1.f / sum;
            s[r * 64 + lane] = e0 * inv;
            s[r * 64 + 32 + lane] = e1 * inv;
        }
    }
    __syncthreads();

    {
        const int tx = tid & 15, ty = tid >> 4;
        float acc[4][5] = {};
        for (int kk = 0; kk < 64; kk++) {
            float sa[4], vb[5];
            #pragma unroll
            for (int i = 0; i < 4; i++) sa[i] = s[(ty * 4 + i) * 64 + kk];
            #pragma unroll
            for (int j = 0; j < 5; j++) vb[j] = v[kk * SP + tx * 5 + j];
            #pragma unroll
            for (int i = 0; i < 4; i++)
                #pragma unroll
                for (int j = 0; j < 5; j++)
                    acc[i][j] += sa[i] * vb[j];
        }
        #pragma unroll
        for (int i = 0; i < 4; i++) {
            long obase = (long)(w * 64 + ty * 4 + i) * HDIM + h * 80 + tx * 5;
            #pragma unroll
            for (int j = 0; j < 5; j++) {
                float val = acc[i][j];
                __nv_bfloat16 hh = __float2bfloat16(val);
                outH[obase + j] = hh;
                outL[obase + j] = __float2bfloat16(val - __bfloat162float(hh));
            }
        }
    }
}

// ---------------- fused (optional add) + RMSNorm, bf16 hi/lo out ----------------
__global__ void __launch_bounds__(256) rmsnorm_kernel(
    const float* __restrict__ a, const float* __restrict__ b,
    const float* __restrict__ w, float* __restrict__ sum_out,
    __nv_bfloat16* __restrict__ nh, __nv_bfloat16* __restrict__ nl)
{
    __shared__ float sv[HDIM];
    __shared__ float red[8];
    __shared__ float s_scale;
    const int row = blockIdx.x, tid = threadIdx.x;
    const long base = (long)row * HDIM;
    float ss = 0.f;
    for (int j = tid; j < HDIM; j += 256) {
        float v = a[base + j];
        if (b) v += b[base + j];
        sv[j] = v;
        if (sum_out) sum_out[base + j] = v;
        ss += v * v;
    }
    #pragma unroll
    for (int o = 16; o > 0; o >>= 1) ss += __shfl_xor_sync(~0u, ss, o);
    if ((tid & 31) == 0) red[tid >> 5] = ss;
    __syncthreads();
    if (tid == 0) {
        float t = 0.f;
        #pragma unroll
        for (int i = 0; i < 8; i++) t += red[i];
        s_scale = rsqrtf(t / (float)HDIM + 1e-6f);
    }
    __syncthreads();
    float sc = s_scale;
    for (int j = tid; j < HDIM; j += 256) {
        float v = sv[j] * sc * w[j];
        __nv_bfloat16 hh = __float2bfloat16(v);
        nh[base + j] = hh;
        nl[base + j] = __float2bfloat16(v - __bfloat162float(hh));
    }
}

// ---------------- SwiGLU with bf16 hi/lo out (padded output stride) ----------------
__global__ void __launch_bounds__(256) swiglu_kernel(
    const float* __restrict__ g, const float* __restrict__ u,
    __nv_bfloat16* __restrict__ oh, __nv_bfloat16* __restrict__ ol,
    int rows, int cols, int ldo)
{
    int i = blockIdx.x * 256 + threadIdx.x;
    int total = rows * cols;
    if (i < total) {
        int r = i / cols;
        int c = i - r * cols;
        float x = g[i];
        float sig = 1.f / (1.f + __expf(-x));
        float v = x * sig * u[i];
        __nv_bfloat16 hh = __float2bfloat16(v);
        long o = (long)r * ldo + c;
        oh[o] = hh;
        ol[o] = __float2bfloat16(v - __bfloat162float(hh));
    }
}

// ---------------- fp32 -> bf16 hi/lo split (contiguous) ----------------
__global__ void __launch_bounds__(256) split_kernel(
    const float4* __restrict__ in, __nv_bfloat16* __restrict__ h,
    __nv_bfloat16* __restrict__ l, long n4)
{
    for (long i = (long)blockIdx.x * 256 + threadIdx.x; i < n4; i += (long)gridDim.x * 256) {
        float4 v = in[i];
        __nv_bfloat16 th[4], tl[4];
        float vv[4] = {v.x, v.y, v.z, v.w};
        #pragma unroll
        for (int j = 0; j < 4; j++) {
            th[j] = __float2bfloat16(vv[j]);
            tl[j] = __float2bfloat16(vv[j] - __bfloat162float(th[j]));
        }
        *reinterpret_cast<uint2*>(h + 4 * i) = *reinterpret_cast<uint2*>(th);
        *reinterpret_cast<uint2*>(l + 4 * i) = *reinterpret_cast<uint2*>(tl);
    }
}

// ---------------- fp32 -> bf16 hi/lo split with padded output stride ----------------
__global__ void __launch_bounds__(256) split_pad_kernel(
    const float* __restrict__ in, __nv_bfloat16* __restrict__ h,
    __nv_bfloat16* __restrict__ l, int rows, int cols, int ldo)
{
    int c4n = cols >> 2;
    long total = (long)rows * c4n;
    for (long i = (long)blockIdx.x * 256 + threadIdx.x; i < total; i += (long)gridDim.x * 256) {
        int r = (int)(i / c4n);
        int c4 = (int)(i - (long)r * c4n);
        float4 v = *reinterpret_cast<const float4*>(in + (long)r * cols + c4 * 4);
        __nv_bfloat16 th[4], tl[4];
        float vv[4] = {v.x, v.y, v.z, v.w};
        #pragma unroll
        for (int j = 0; j < 4; j++) {
            th[j] = __float2bfloat16(vv[j]);
            tl[j] = __float2bfloat16(vv[j] - __bfloat162float(th[j]));
        }
        long o = (long)r * ldo + c4 * 4;
        *reinterpret_cast<uint2*>(h + o) = *reinterpret_cast<uint2*>(th);
        *reinterpret_cast<uint2*>(l + o) = *reinterpret_cast<uint2*>(tl);
    }
}

// ---------------- host ----------------
static inline dim3 ggrid(int M, int N) { return dim3((N + 127) / 128, (M + 127) / 128); }

static inline void do_split(const float* src, __nv_bfloat16* h, __nv_bfloat16* l, long n) {
    long n4 = n / 4;
    int blocks = (int)((n4 + 255) / 256);
    if (blocks > 16384) blocks = 16384;
    split_kernel<<<blocks, 256>>>((const float4*)src, h, l, n4);
}
static inline void do_split_pad(const float* src, __nv_bfloat16* h, __nv_bfloat16* l,
                                int rows, int cols, int ldo) {
    long total = (long)rows * (cols / 4);
    int blocks = (int)((total + 255) / 256);
    if (blocks > 16384) blocks = 16384;
    split_pad_kernel<<<blocks, 256>>>(src, h, l, rows, cols, ldo);
}

extern "C" void kernel_launch(void* const* d_in, const int* in_sizes, int n_in,
                              void* d_out, int out_size)
{
    const float* x       = (const float*)d_in[0];
    const float* cosb    = (const float*)d_in[1];
    const float* sinb    = (const float*)d_in[2];
    const float* patch_w = (const float*)d_in[3];
    const float* norm1_w = (const float*)d_in[4];
    const float* norm2_w = (const float*)d_in[5];
    const float* qkv_w   = (const float*)d_in[6];
    const float* qkv_b   = (const float*)d_in[7];
    const float* proj_w  = (const float*)d_in[8];
    const float* proj_b  = (const float*)d_in[9];
    const float* gate_w  = (const float*)d_in[10];
    const float* gate_b  = (const float*)d_in[11];
    const float* up_w    = (const float*)d_in[12];
    const float* up_b    = (const float*)d_in[13];
    const float* down_w  = (const float*)d_in[14];
    const float* down_b  = (const float*)d_in[15];
    const float* lnq_w   = (const float*)d_in[16];
    const float* m0_w    = (const float*)d_in[17];
    const float* m0_b    = (const float*)d_in[18];
    const float* m2_w    = (const float*)d_in[19];
    const float* m2_b    = (const float*)d_in[20];

    float* fs = nullptr;
    __nv_bfloat16* bs = nullptr;
    cudaGetSymbolAddress((void**)&fs, g_f32);
    cudaGetSymbolAddress((void**)&bs, g_bf16);

    float* pX    = fs + F_X;
    float* pRES  = fs + F_RES;
    float* pHB   = fs + F_HB;
    float* pQKV  = fs + F_QKV;
    float* pGATE = fs + F_GATE;
    float* pUP   = fs + F_UP;

    __nv_bfloat16 *xH = bs+B_XH, *xL = bs+B_XL;
    __nv_bfloat16 *nH = bs+B_NH, *nL = bs+B_NL;
    __nv_bfloat16 *aH = bs+B_AH, *aL = bs+B_AL;
    __nv_bfloat16 *sH = bs+B_SH, *sL = bs+B_SL;
    __nv_bfloat16 *pwH = bs+B_PW,  *pwL = pwH + SZ_PW;
    __nv_bfloat16 *qwH = bs+B_QW,  *qwL = qwH + SZ_QW;
    __nv_bfloat16 *prH = bs+B_PRW, *prL = prH + SZ_PRW;
    __nv_bfloat16 *gwH = bs+B_GW,  *gwL = gwH + SZ_GWP;
    __nv_bfloat16 *uwH = bs+B_UW,  *uwL = uwH + SZ_GWP;
    __nv_bfloat16 *dwH = bs+B_DW,  *dwL = dwH + SZ_DW;
    __nv_bfloat16 *m0H = bs+B_M0W, *m0L = m0H + SZ_M0W;
    __nv_bfloat16 *m2H = bs+B_M2W, *m2L = m2H + SZ_M2W;

    cudaFuncSetAttribute(tcgemm_kernel<E_NONE>, cudaFuncAttributeMaxDynamicSharedMemorySize, GEMM_SMEM);
    cudaFuncSetAttribute(tcgemm_kernel<E_BIAS>, cudaFuncAttributeMaxDynamicSharedMemorySize, GEMM_SMEM);
    cudaFuncSetAttribute(tcgemm_kernel<E_BIAS_RES>, cudaFuncAttributeMaxDynamicSharedMemorySize, GEMM_SMEM);
    cudaFuncSetAttribute(tcgemm_kernel<E_GELU_SPLIT>, cudaFuncAttributeMaxDynamicSharedMemorySize, GEMM_SMEM);
    cudaFuncSetAttribute(attn_kernel, cudaFuncAttributeMaxDynamicSharedMemorySize, ATTN_SMEM);

    do_split(x,       xH,  xL,  SZ_XS);
    do_split(patch_w, pwH, pwL, SZ_PW);
    do_split(qkv_w,   qwH, qwL, SZ_QW);
    do_split(proj_w,  prH, prL, SZ_PRW);
    do_split_pad(gate_w, gwH, gwL, NBLK * HDIM, MHID, MH_P);

    // patch embed: [8192,1176]@[1176,1280]   (launch #6 - profiled)
    tcgemm_kernel<E_NONE><<<ggrid(LTOK, HDIM), GT, GEMM_SMEM>>>(
        xH, xL, pwH, pwL, nullptr, nullptr, pX, nullptr, nullptr,
        LTOK, HDIM, PDIM, PDIM, HDIM, HDIM);

    do_split_pad(up_w,   uwH, uwL, NBLK * HDIM, MHID, MH_P);
    do_split(down_w,  dwH, dwL, SZ_DW);
    do_split(m0_w,    m0H, m0L, SZ_M0W);
    do_split(m2_w,    m2H, m2L, SZ_M2W);
    cudaMemsetAsync(pRES, 0, SZ_LH * sizeof(float));

    for (int d = 0; d < NBLK; d++) {
        rmsnorm_kernel<<<LTOK, 256>>>(pX, pRES, norm1_w + (long)d * HDIM, pHB, nH, nL);
        tcgemm_kernel<E_BIAS><<<ggrid(LTOK, 3 * HDIM), GT, GEMM_SMEM>>>(
            nH, nL, qwH + (long)d * HDIM * 3 * HDIM, qwL + (long)d * HDIM * 3 * HDIM,
            qkv_b + (long)d * 3 * HDIM, nullptr, pQKV, nullptr, nullptr,
            LTOK, 3 * HDIM, HDIM, HDIM, 3 * HDIM, 3 * HDIM);
        attn_kernel<<<NWIN * NHEAD, 256, ATTN_SMEM>>>(pQKV, cosb, sinb, aH, aL);
        tcgemm_kernel<E_BIAS_RES><<<ggrid(LTOK, HDIM), GT, GEMM_SMEM>>>(
            aH, aL, prH + (long)d * HDIM * HDIM, prL + (long)d * HDIM * HDIM,
            proj_b + (long)d * HDIM, pHB, pRES, nullptr, nullptr,
            LTOK, HDIM, HDIM, HDIM, HDIM, HDIM);
        rmsnorm_kernel<<<LTOK, 256>>>(pRES, nullptr, norm2_w + (long)d * HDIM, nullptr, nH, nL);
        tcgemm_kernel<E_BIAS><<<ggrid(LTOK, MHID), GT, GEMM_SMEM>>>(
            nH, nL, gwH + (long)d * HDIM * MH_P, gwL + (long)d * HDIM * MH_P,
            gate_b + (long)d * MHID, nullptr, pGATE, nullptr, nullptr,
            LTOK, MHID, HDIM, HDIM, MH_P, MHID);
        tcgemm_kernel<E_BIAS><<<ggrid(LTOK, MHID), GT, GEMM_SMEM>>>(
            nH, nL, uwH + (long)d * HDIM * MH_P, uwL + (long)d * HDIM * MH_P,
            up_b + (long)d * MHID, nullptr, pUP, nullptr, nullptr,
            LTOK, MHID, HDIM, HDIM, MH_P, MHID);
        swiglu_kernel<<<(unsigned)(((long)LTOK * MHID + 255) / 256), 256>>>(
            pGATE, pUP, sH, sL, LTOK, MHID, MH_P);
        tcgemm_kernel<E_BIAS><<<ggrid(LTOK, HDIM), GT, GEMM_SMEM>>>(
            sH, sL, dwH + (long)d * MHID * HDIM, dwL + (long)d * MHID * HDIM,
            down_b + (long)d * HDIM, nullptr, pX, nullptr, nullptr,
            LTOK, HDIM, MHID, MH_P, HDIM, HDIM);
    }

    // merger
    rmsnorm_kernel<<<LTOK, 256>>>(pX, pRES, lnq_w, nullptr, nH, nL);
    tcgemm_kernel<E_GELU_SPLIT><<<ggrid(LMERG, H4), GT, GEMM_SMEM>>>(
        nH, nL, m0H, m0L, m0_b, nullptr, nullptr, aH, aL,
        LMERG, H4, H4, H4, H4, H4);
    tcgemm_kernel<E_BIAS><<<ggrid(LMERG, DMODEL), GT, GEMM_SMEM>>>(
        aH, aL, m2H, m2L, m2_b, nullptr, (float*)d_out, nullptr, nullptr,
        LMERG, DMODEL, H4, H4, DMODEL, DMODEL);
}

// round 11
// speedup vs baseline: 2.2931x; 1.0433x over previous
#include <cuda_runtime.h>
#include <cuda_bf16.h>
#include <math.h>
#include <stdint.h>

// ---------------- problem constants ----------------
#define LTOK 8192
#define HDIM 1280
#define NHEAD 16
#define HEADD 80
#define MHID 3420
#define MH_P 3424          // padded leading dim (16B-aligned bf16 rows)
#define GU_N 6848          // merged gate|up width (2 * MH_P)
#define NBLK 4
#define NWIN 128
#define PDIM 1176
#define DMODEL 3584
#define H4 5120
#define LMERG 2048

// ---------------- fp32 scratch ----------------
static constexpr long SZ_LH  = (long)LTOK * HDIM;
static constexpr long SZ_L3H = (long)LTOK * 3 * HDIM;

static constexpr long F_X    = 0;
static constexpr long F_RES  = F_X   + SZ_LH;
static constexpr long F_HB   = F_RES + SZ_LH;
static constexpr long F_QKV  = F_HB  + SZ_LH;
static constexpr long F_GU   = F_QKV + SZ_L3H;           // [LTOK][GU_N]
static constexpr long F_TOTAL = F_GU + (long)LTOK * GU_N;
__device__ float g_f32[F_TOTAL];

__device__ float g_bias[NBLK * GU_N];

// ---------------- bf16 scratch (hi/lo pairs) ----------------
static constexpr long SZ_XS  = (long)LTOK * PDIM;
static constexpr long SZ_PW  = (long)PDIM * HDIM;
static constexpr long SZ_QW  = (long)NBLK * HDIM * 3*HDIM;
static constexpr long SZ_PRW = (long)NBLK * HDIM * HDIM;
static constexpr long SZ_GU  = (long)NBLK * HDIM * GU_N;   // merged gate|up
static constexpr long SZ_DW  = (long)NBLK * MHID * HDIM;
static constexpr long SZ_M0W = (long)H4 * H4;
static constexpr long SZ_M2W = (long)H4 * DMODEL;
static constexpr long SZ_SHP = (long)LTOK * MH_P;          // padded swiglu out

static constexpr long B_XH  = 0;
static constexpr long B_XL  = B_XH + SZ_XS;
static constexpr long B_NH  = B_XL + SZ_XS;
static constexpr long B_NL  = B_NH + SZ_LH;
static constexpr long B_AH  = B_NL + SZ_LH;
static constexpr long B_AL  = B_AH + SZ_LH;
static constexpr long B_SH  = B_AL + SZ_LH;
static constexpr long B_SL  = B_SH + SZ_SHP;
static constexpr long B_PW  = B_SL + SZ_SHP;
static constexpr long B_QW  = B_PW + 2*SZ_PW;
static constexpr long B_PRW = B_QW + 2*SZ_QW;
static constexpr long B_GUH = B_PRW + 2*SZ_PRW;
static constexpr long B_GUL = B_GUH + SZ_GU;
static constexpr long B_DW  = B_GUL + SZ_GU;
static constexpr long B_M0W = B_DW + 2*SZ_DW;
static constexpr long B_M2W = B_M0W + 2*SZ_M0W;
static constexpr long B_TOTAL = B_M2W + 2*SZ_M2W;
__device__ __nv_bfloat16 g_bf16[B_TOTAL];

// ---------------- PTX helpers (base sm_103 target only!) ----------------
__device__ __forceinline__ uint32_t smem_to_u32(const void* p) {
    uint32_t a;
    asm("{ .reg .u64 t; cvta.to.shared.u64 t, %1; cvt.u32.u64 %0, t; }" : "=r"(a) : "l"(p));
    return a;
}
__device__ __forceinline__ void cp16(uint32_t dst, const void* src, int bytes) {
    asm volatile("cp.async.cg.shared.global [%0], [%1], 16, %2;"
                 :: "r"(dst), "l"(src), "r"(bytes));
}
#define CP_COMMIT() asm volatile("cp.async.commit_group;" ::: "memory")
#define CP_WAIT2()  asm volatile("cp.async.wait_group 2;" ::: "memory")

__device__ __forceinline__ void ldsm_x4(uint32_t r[4], uint32_t addr) {
    asm volatile("ldmatrix.sync.aligned.m8n8.x4.shared.b16 {%0,%1,%2,%3}, [%4];"
                 : "=r"(r[0]), "=r"(r[1]), "=r"(r[2]), "=r"(r[3]) : "r"(addr));
}
__device__ __forceinline__ void ldsm_x4t(uint32_t r[4], uint32_t addr) {
    asm volatile("ldmatrix.sync.aligned.m8n8.x4.trans.shared.b16 {%0,%1,%2,%3}, [%4];"
                 : "=r"(r[0]), "=r"(r[1]), "=r"(r[2]), "=r"(r[3]) : "r"(addr));
}
__device__ __forceinline__ void mma_bf16(float c[4], const uint32_t a[4],
                                         uint32_t b0, uint32_t b1) {
    asm volatile(
        "mma.sync.aligned.m16n8k16.row.col.f32.bf16.bf16.f32 "
        "{%0,%1,%2,%3}, {%4,%5,%6,%7}, {%8,%9}, {%0,%1,%2,%3};"
        : "+f"(c[0]), "+f"(c[1]), "+f"(c[2]), "+f"(c[3])
        : "r"(a[0]), "r"(a[1]), "r"(a[2]), "r"(a[3]), "r"(b0), "r"(b1));
}

// ---------------- tensor-core GEMM (bf16x3 split, fp32 accum) ----------------
enum { E_NONE = 0, E_BIAS = 1, E_BIAS_RES = 2, E_GELU_SPLIT = 3 };

#define A_STRIDE 40
#define B_STRIDE 136
#define A_TILE_B (128 * A_STRIDE * 2)      // 10240
#define B_TILE_B (32 * B_STRIDE * 2)       // 8704
#define STAGE_B  (2 * A_TILE_B + 2 * B_TILE_B)  // 37888
#define OFF_AH 0
#define OFF_AL A_TILE_B
#define OFF_BH (2 * A_TILE_B)
#define OFF_BL (2 * A_TILE_B + B_TILE_B)
#define GEMM_SMEM (3 * STAGE_B)            // 113664
#define GT 256

template<int EPI>
__global__ void __launch_bounds__(GT, 2) tcgemm_kernel(
    const __nv_bfloat16* __restrict__ Ah, const __nv_bfloat16* __restrict__ Al,
    const __nv_bfloat16* __restrict__ Bh, const __nv_bfloat16* __restrict__ Bl,
    const float* __restrict__ bias, const float* __restrict__ res,
    float* __restrict__ C, __nv_bfloat16* __restrict__ Oh, __nv_bfloat16* __restrict__ Ol,
    int M, int N, int K, int lda, int ldb, int ldc)
{
    extern __shared__ __align__(16) char sm[];
    const uint32_t smem_u = smem_to_u32(sm);
    const int tid = threadIdx.x;
    const int lane = tid & 31, wid = tid >> 5;
    const int wm = wid >> 2, wn = wid & 3;        // 2(M) x 4(N) warp grid
    const int row0 = blockIdx.y * 128, col0 = blockIdx.x * 128;

    const int nc = (K + 31) / 32;

    auto load_stage = [&](int st, int c) {
        const uint32_t sbase = smem_u + st * STAGE_B;
        const int k0 = c * 32;
        #pragma unroll
        for (int h = 0; h < 2; ++h) {
            const __nv_bfloat16* src = h ? Al : Ah;
            const uint32_t dbase = sbase + (h ? OFF_AL : OFF_AH);
            #pragma unroll
            for (int it = 0; it < 2; ++it) {
                int e = tid + it * 256;
                int r = e >> 2, q = e & 3;
                int gr = row0 + r;
                int gk = k0 + q * 8;
                int bytes = (K - gk) * 2;
                bytes = bytes < 0 ? 0 : (bytes > 16 ? 16 : bytes);
                const __nv_bfloat16* g = src + (long)gr * lda + (bytes > 0 ? gk : 0);
                cp16(dbase + r * (A_STRIDE * 2) + q * 16, g, bytes);
            }
        }
        #pragma unroll
        for (int h = 0; h < 2; ++h) {
            const __nv_bfloat16* src = h ? Bl : Bh;
            const uint32_t dbase = sbase + (h ? OFF_BL : OFF_BH);
            #pragma unroll
            for (int it = 0; it < 2; ++it) {
                int e = tid + it * 256;
                int r = e >> 4, q = e & 15;
                int gk = k0 + r;
                int gc = col0 + q * 8;
                int bytes = (N - gc) * 2;
                bytes = bytes < 0 ? 0 : (bytes > 16 ? 16 : bytes);
                if (gk >= K) bytes = 0;
                const __nv_bfloat16* g = src + (long)(gk < K ? gk : 0) * ldb + (bytes > 0 ? gc : 0);
                cp16(dbase + r * (B_STRIDE * 2) + q * 16, g, bytes);
            }
        }
    };

    const int a_row = lane & 15;
    const int a_kh = (lane >> 4) * 8;
    const int b_g = lane >> 3, b_l = lane & 7;
    const int b_k = (b_g & 1) * 8 + b_l;
    const int b_n = (b_g >> 1) * 8;

    float acc[4][4][4];
    #pragma unroll
    for (int i = 0; i < 4; ++i)
        #pragma unroll
        for (int j = 0; j < 4; ++j)
            #pragma unroll
            for (int r = 0; r < 4; ++r) acc[i][j][r] = 0.f;

    #pragma unroll
    for (int s = 0; s < 3; ++s) {
        if (s < nc) load_stage(s, s);
        CP_COMMIT();
    }

    for (int c = 0; c < nc; ++c) {
        CP_WAIT2();
        __syncthreads();
        const int st = c % 3;
        const uint32_t sbase = smem_u + st * STAGE_B;
        const uint32_t aB[2] = { sbase + OFF_AH, sbase + OFF_AL };
        const uint32_t bB[2] = { sbase + OFF_BH, sbase + OFF_BL };

        #pragma unroll
        for (int ks = 0; ks < 2; ++ks) {
            uint32_t af[2][4][4];
            #pragma unroll
            for (int h = 0; h < 2; ++h)
                #pragma unroll
                for (int i = 0; i < 4; ++i)
                    ldsm_x4(af[h][i],
                        aB[h] + 2u * ((wm * 64 + i * 16 + a_row) * A_STRIDE + ks * 16 + a_kh));
            #pragma unroll
            for (int j2 = 0; j2 < 2; ++j2) {
                uint32_t b0[4], b1[4];
                uint32_t boff = 2u * ((ks * 16 + b_k) * B_STRIDE + wn * 32 + j2 * 16 + b_n);
                ldsm_x4t(b0, bB[0] + boff);
                ldsm_x4t(b1, bB[1] + boff);
                #pragma unroll
                for (int i = 0; i < 4; ++i) {
                    mma_bf16(acc[i][2*j2],   af[0][i], b0[0], b0[1]);
                    mma_bf16(acc[i][2*j2+1], af[0][i], b0[2], b0[3]);
                    mma_bf16(acc[i][2*j2],   af[0][i], b1[0], b1[1]);
                    mma_bf16(acc[i][2*j2+1], af[0][i], b1[2], b1[3]);
                    mma_bf16(acc[i][2*j2],   af[1][i], b0[0], b0[1]);
                    mma_bf16(acc[i][2*j2+1], af[1][i], b0[2], b0[3]);
                }
            }
        }
        __syncthreads();
        if (c + 3 < nc) load_stage(st, c + 3);
        CP_COMMIT();
    }

    const int g = lane >> 2, t = lane & 3;
    #pragma unroll
    for (int i = 0; i < 4; ++i) {
        #pragma unroll
        for (int j = 0; j < 4; ++j) {
            int col = col0 + wn * 32 + j * 8 + t * 2;
            if (col >= N) continue;
            float b0 = 0.f, b1 = 0.f;
            if (EPI != E_NONE) { b0 = bias[col]; b1 = bias[col + 1]; }
            #pragma unroll
            for (int rr = 0; rr < 2; ++rr) {
                int row = row0 + wm * 64 + i * 16 + g + rr * 8;
                if (row >= M) continue;
                float v0 = acc[i][j][rr * 2 + 0] + b0;
                float v1 = acc[i][j][rr * 2 + 1] + b1;
                long idx = (long)row * ldc + col;
                if (EPI == E_BIAS_RES) { v0 += res[idx]; v1 += res[idx + 1]; }
                if (EPI == E_GELU_SPLIT) {
                    v0 = 0.5f * v0 * (1.f + erff(v0 * 0.70710678118654752f));
                    v1 = 0.5f * v1 * (1.f + erff(v1 * 0.70710678118654752f));
                    __nv_bfloat16 h0 = __float2bfloat16(v0);
                    __nv_bfloat16 h1 = __float2bfloat16(v1);
                    Oh[idx] = h0; Oh[idx + 1] = h1;
                    Ol[idx]     = __float2bfloat16(v0 - __bfloat162float(h0));
                    Ol[idx + 1] = __float2bfloat16(v1 - __bfloat162float(h1));
                } else {
                    float2 o = make_float2(v0, v1);
                    *reinterpret_cast<float2*>(C + idx) = o;
                }
            }
        }
    }
}

// ---------------- fused windowed attention with inline RoPE (fp32) ----------------
#define SP 81
#define ATTN_SMEM (3 * 64 * SP * 4)

__global__ void __launch_bounds__(256) attn_kernel(
    const float* __restrict__ qkv, const float* __restrict__ cosb,
    const float* __restrict__ sinb, __nv_bfloat16* __restrict__ outH,
    __nv_bfloat16* __restrict__ outL)
{
    extern __shared__ float smf[];
    float* q = smf;
    float* k = smf + 64 * SP;
    float* v = smf + 2 * 64 * SP;
    float* s = smf;                 // aliases q (dead after QK phase)

    const int w = blockIdx.x >> 4;
    const int h = blockIdx.x & 15;
    const int tid = threadIdx.x;
    const float scale = 0.11180339887498949f;

    for (int e = tid; e < 64 * 80; e += 256) {
        int t = e / 80, j = e % 80;
        int l = w * 64 + t;
        long base = (long)l * (3 * HDIM) + h * 80;
        float c = cosb[l * 80 + j], sn = sinb[l * 80 + j];
        float qv = qkv[base + j];
        float qr = (j < 40) ? -qkv[base + j + 40] : qkv[base + j - 40];
        q[t * SP + j] = qv * c + qr * sn;
        float kv = qkv[base + HDIM + j];
        float kr = (j < 40) ? -qkv[base + HDIM + j + 40] : qkv[base + HDIM + j - 40];
        k[t * SP + j] = kv * c + kr * sn;
        v[t * SP + j] = qkv[base + 2 * HDIM + j];
    }
    __syncthreads();

    {
        const int tx = tid & 15, ty = tid >> 4;
        float acc[4][4] = {};
        for (int d = 0; d < 80; d++) {
            float qa[4], kb[4];
            #pragma unroll
            for (int i = 0; i < 4; i++) qa[i] = q[(ty * 4 + i) * SP + d];
            #pragma unroll
            for (int j = 0; j < 4; j++) kb[j] = k[(tx * 4 + j) * SP + d];
            #pragma unroll
            for (int i = 0; i < 4; i++)
                #pragma unroll
                for (int j = 0; j < 4; j++)
                    acc[i][j] += qa[i] * kb[j];
        }
        __syncthreads();   // all reads of q complete before s overwrites it
        #pragma unroll
        for (int i = 0; i < 4; i++)
            #pragma unroll
            for (int j = 0; j < 4; j++)
                s[(ty * 4 + i) * 64 + tx * 4 + j] = acc[i][j] * scale;
    }
    __syncthreads();

    {
        const int warp = tid >> 5, lane = tid & 31;
        for (int r = warp; r < 64; r += 8) {
            float x0 = s[r * 64 + lane], x1 = s[r * 64 + 32 + lane];
            float mx = fmaxf(x0, x1);
            #pragma unroll
            for (int o = 16; o > 0; o >>= 1) mx = fmaxf(mx, __shfl_xor_sync(~0u, mx, o));
            float e0 = __expf(x0 - mx), e1 = __expf(x1 - mx);
            float sum = e0 + e1;
            #pragma unroll
            for (int o = 16; o > 0; o >>= 1) sum += __shfl_xor_sync(~0u, sum, o);
            float inv = 1.f / sum;
            s[r * 64 + lane] = e0 * inv;
            s[r * 64 + 32 + lane] = e1 * inv;
        }
    }
    __syncthreads();

    {
        const int tx = tid & 15, ty = tid >> 4;
        float acc[4][5] = {};
        for (int kk = 0; kk < 64; kk++) {
            float sa[4], vb[5];
            #pragma unroll
            for (int i = 0; i < 4; i++) sa[i] = s[(ty * 4 + i) * 64 + kk];
            #pragma unroll
            for (int j = 0; j < 5; j++) vb[j] = v[kk * SP + tx * 5 + j];
            #pragma unroll
            for (int i = 0; i < 4; i++)
                #pragma unroll
                for (int j = 0; j < 5; j++)
                    acc[i][j] += sa[i] * vb[j];
        }
        #pragma unroll
        for (int i = 0; i < 4; i++) {
            long obase = (long)(w * 64 + ty * 4 + i) * HDIM + h * 80 + tx * 5;
            #pragma unroll
            for (int j = 0; j < 5; j++) {
                float val = acc[i][j];
                __nv_bfloat16 hh = __float2bfloat16(val);
                outH[obase + j] = hh;
                outL[obase + j] = __float2bfloat16(val - __bfloat162float(hh));
            }
        }
    }
}

// ---------------- fused (optional add) + RMSNorm, bf16 hi/lo out ----------------
__global__ void __launch_bounds__(256) rmsnorm_kernel(
    const float* __restrict__ a, const float* __restrict__ b,
    const float* __restrict__ w, float* __restrict__ sum_out,
    __nv_bfloat16* __restrict__ nh, __nv_bfloat16* __restrict__ nl)
{
    __shared__ float sv[HDIM];
    __shared__ float red[8];
    __shared__ float s_scale;
    const int row = blockIdx.x, tid = threadIdx.x;
    const long base = (long)row * HDIM;
    float ss = 0.f;
    for (int j = tid; j < HDIM; j += 256) {
        float v = a[base + j];
        if (b) v += b[base + j];
        sv[j] = v;
        if (sum_out) sum_out[base + j] = v;
        ss += v * v;
    }
    #pragma unroll
    for (int o = 16; o > 0; o >>= 1) ss += __shfl_xor_sync(~0u, ss, o);
    if ((tid & 31) == 0) red[tid >> 5] = ss;
    __syncthreads();
    if (tid == 0) {
        float t = 0.f;
        #pragma unroll
        for (int i = 0; i < 8; i++) t += red[i];
        s_scale = rsqrtf(t / (float)HDIM + 1e-6f);
    }
    __syncthreads();
    float sc = s_scale;
    for (int j = tid; j < HDIM; j += 256) {
        float v = sv[j] * sc * w[j];
        __nv_bfloat16 hh = __float2bfloat16(v);
        nh[base + j] = hh;
        nl[base + j] = __float2bfloat16(v - __bfloat162float(hh));
    }
}

// ---------------- SwiGLU over merged [row][GU_N] buffer, bf16 hi/lo out ----------------
__global__ void __launch_bounds__(256) swiglu_kernel(
    const float* __restrict__ gu,
    __nv_bfloat16* __restrict__ oh, __nv_bfloat16* __restrict__ ol)
{
    const int row = blockIdx.x, tid = threadIdx.x;
    const long gbase = (long)row * GU_N;
    const long obase = (long)row * MH_P;
    for (int c = tid * 4; c < MHID; c += 1024) {
        float4 gv = *reinterpret_cast<const float4*>(gu + gbase + c);
        float4 uv = *reinterpret_cast<const float4*>(gu + gbase + MH_P + c);
        float gr[4] = {gv.x, gv.y, gv.z, gv.w};
        float ur[4] = {uv.x, uv.y, uv.z, uv.w};
        __nv_bfloat16 th[4], tl[4];
        #pragma unroll
        for (int j = 0; j < 4; j++) {
            float x = gr[j];
            float v = (c + j < MHID) ? (x / (1.f + __expf(-x)) * ur[j]) : 0.f;
            __nv_bfloat16 hh = __float2bfloat16(v);
            th[j] = hh;
            tl[j] = __float2bfloat16(v - __bfloat162float(hh));
        }
        *reinterpret_cast<uint2*>(oh + obase + c) = *reinterpret_cast<uint2*>(th);
        *reinterpret_cast<uint2*>(ol + obase + c) = *reinterpret_cast<uint2*>(tl);
    }
}

// ---------------- merged gate|up bias fill ----------------
__global__ void __launch_bounds__(256) fill_bias_kernel(
    const float* __restrict__ gate_b, const float* __restrict__ up_b, float* __restrict__ out)
{
    int i = blockIdx.x * 256 + threadIdx.x;
    if (i >= NBLK * GU_N) return;
    int d = i / GU_N, c = i - d * GU_N;
    float v = 0.f;
    if (c < MHID) v = gate_b[d * MHID + c];
    else if (c >= MH_P && c - MH_P < MHID) v = up_b[d * MHID + (c - MH_P)];
    out[i] = v;
}

// ---------------- fp32 -> bf16 hi/lo split (contiguous) ----------------
__global__ void __launch_bounds__(256) split_kernel(
    const float4* __restrict__ in, __nv_bfloat16* __restrict__ h,
    __nv_bfloat16* __restrict__ l, long n4)
{
    for (long i = (long)blockIdx.x * 256 + threadIdx.x; i < n4; i += (long)gridDim.x * 256) {
        float4 v = in[i];
        __nv_bfloat16 th[4], tl[4];
        float vv[4] = {v.x, v.y, v.z, v.w};
        #pragma unroll
        for (int j = 0; j < 4; j++) {
            th[j] = __float2bfloat16(vv[j]);
            tl[j] = __float2bfloat16(vv[j] - __bfloat162float(th[j]));
        }
        *reinterpret_cast<uint2*>(h + 4 * i) = *reinterpret_cast<uint2*>(th);
        *reinterpret_cast<uint2*>(l + 4 * i) = *reinterpret_cast<uint2*>(tl);
    }
}

// ---------------- fp32 -> bf16 hi/lo split with padded output stride ----------------
__global__ void __launch_bounds__(256) split_pad_kernel(
    const float* __restrict__ in, __nv_bfloat16* __restrict__ h,
    __nv_bfloat16* __restrict__ l, int rows, int cols, int ldo)
{
    int c4n = cols >> 2;
    long total = (long)rows * c4n;
    for (long i = (long)blockIdx.x * 256 + threadIdx.x; i < total; i += (long)gridDim.x * 256) {
        int r = (int)(i / c4n);
        int c4 = (int)(i - (long)r * c4n);
        float4 v = *reinterpret_cast<const float4*>(in + (long)r * cols + c4 * 4);
        __nv_bfloat16 th[4], tl[4];
        float vv[4] = {v.x, v.y, v.z, v.w};
        #pragma unroll
        for (int j = 0; j < 4; j++) {
            th[j] = __float2bfloat16(vv[j]);
            tl[j] = __float2bfloat16(vv[j] - __bfloat162float(th[j]));
        }
        long o = (long)r * ldo + c4 * 4;
        *reinterpret_cast<uint2*>(h + o) = *reinterpret_cast<uint2*>(th);
        *reinterpret_cast<uint2*>(l + o) = *reinterpret_cast<uint2*>(tl);
    }
}

// ---------------- host ----------------
static inline dim3 ggrid(int M, int N) { return dim3((N + 127) / 128, (M + 127) / 128); }

static inline void do_split(const float* src, __nv_bfloat16* h, __nv_bfloat16* l, long n) {
    long n4 = n / 4;
    int blocks = (int)((n4 + 255) / 256);
    if (blocks > 16384) blocks = 16384;
    split_kernel<<<blocks, 256>>>((const float4*)src, h, l, n4);
}
static inline void do_split_pad(const float* src, __nv_bfloat16* h, __nv_bfloat16* l,
                                int rows, int cols, int ldo) {
    long total = (long)rows * (cols / 4);
    int blocks = (int)((total + 255) / 256);
    if (blocks > 16384) blocks = 16384;
    split_pad_kernel<<<blocks, 256>>>(src, h, l, rows, cols, ldo);
}

extern "C" void kernel_launch(void* const* d_in, const int* in_sizes, int n_in,
                              void* d_out, int out_size)
{
    const float* x       = (const float*)d_in[0];
    const float* cosb    = (const float*)d_in[1];
    const float* sinb    = (const float*)d_in[2];
    const float* patch_w = (const float*)d_in[3];
    const float* norm1_w = (const float*)d_in[4];
    const float* norm2_w = (const float*)d_in[5];
    const float* qkv_w   = (const float*)d_in[6];
    const float* qkv_b   = (const float*)d_in[7];
    const float* proj_w  = (const float*)d_in[8];
    const float* proj_b  = (const float*)d_in[9];
    const float* gate_w  = (const float*)d_in[10];
    const float* gate_b  = (const float*)d_in[11];
    const float* up_w    = (const float*)d_in[12];
    const float* up_b    = (const float*)d_in[13];
    const float* down_w  = (const float*)d_in[14];
    const float* down_b  = (const float*)d_in[15];
    const float* lnq_w   = (const float*)d_in[16];
    const float* m0_w    = (const float*)d_in[17];
    const float* m0_b    = (const float*)d_in[18];
    const float* m2_w    = (const float*)d_in[19];
    const float* m2_b    = (const float*)d_in[20];

    float* fs = nullptr;
    __nv_bfloat16* bs = nullptr;
    float* gub = nullptr;
    cudaGetSymbolAddress((void**)&fs, g_f32);
    cudaGetSymbolAddress((void**)&bs, g_bf16);
    cudaGetSymbolAddress((void**)&gub, g_bias);

    float* pX    = fs + F_X;
    float* pRES  = fs + F_RES;
    float* pHB   = fs + F_HB;
    float* pQKV  = fs + F_QKV;
    float* pGU   = fs + F_GU;

    __nv_bfloat16 *xH = bs+B_XH, *xL = bs+B_XL;
    __nv_bfloat16 *nH = bs+B_NH, *nL = bs+B_NL;
    __nv_bfloat16 *aH = bs+B_AH, *aL = bs+B_AL;
    __nv_bfloat16 *sH = bs+B_SH, *sL = bs+B_SL;
    __nv_bfloat16 *pwH = bs+B_PW,  *pwL = pwH + SZ_PW;
    __nv_bfloat16 *qwH = bs+B_QW,  *qwL = qwH + SZ_QW;
    __nv_bfloat16 *prH = bs+B_PRW, *prL = prH + SZ_PRW;
    __nv_bfloat16 *guH = bs+B_GUH, *guL = bs+B_GUL;
    __nv_bfloat16 *dwH = bs+B_DW,  *dwL = dwH + SZ_DW;
    __nv_bfloat16 *m0H = bs+B_M0W, *m0L = m0H + SZ_M0W;
    __nv_bfloat16 *m2H = bs+B_M2W, *m2L = m2H + SZ_M2W;

    cudaFuncSetAttribute(tcgemm_kernel<E_NONE>, cudaFuncAttributeMaxDynamicSharedMemorySize, GEMM_SMEM);
    cudaFuncSetAttribute(tcgemm_kernel<E_BIAS>, cudaFuncAttributeMaxDynamicSharedMemorySize, GEMM_SMEM);
    cudaFuncSetAttribute(tcgemm_kernel<E_BIAS_RES>, cudaFuncAttributeMaxDynamicSharedMemorySize, GEMM_SMEM);
    cudaFuncSetAttribute(tcgemm_kernel<E_GELU_SPLIT>, cudaFuncAttributeMaxDynamicSharedMemorySize, GEMM_SMEM);
    cudaFuncSetAttribute(attn_kernel, cudaFuncAttributeMaxDynamicSharedMemorySize, ATTN_SMEM);

    do_split(x,       xH,  xL,  SZ_XS);
    do_split(patch_w, pwH, pwL, SZ_PW);
    do_split(qkv_w,   qwH, qwL, SZ_QW);
    do_split(proj_w,  prH, prL, SZ_PRW);
    // merged gate|up weights: gate -> cols [0,3424), up -> cols [3424,6848)
    do_split_pad(gate_w, guH, guL, NBLK * HDIM, MHID, GU_N);

    // patch embed (launch #6 for ncu window)
    tcgemm_kernel<E_NONE><<<ggrid(LTOK, HDIM), GT, GEMM_SMEM>>>(
        xH, xL, pwH, pwL, nullptr, nullptr, pX, nullptr, nullptr,
        LTOK, HDIM, PDIM, PDIM, HDIM, HDIM);

    do_split_pad(up_w, guH + MH_P, guL + MH_P, NBLK * HDIM, MHID, GU_N);
    do_split(down_w,  dwH, dwL, SZ_DW);
    do_split(m0_w,    m0H, m0L, SZ_M0W);
    do_split(m2_w,    m2H, m2L, SZ_M2W);
    fill_bias_kernel<<<(NBLK * GU_N + 255) / 256, 256>>>(gate_b, up_b, gub);

    for (int d = 0; d < NBLK; d++) {
        rmsnorm_kernel<<<LTOK, 256>>>(pX, d == 0 ? nullptr : pRES,
                                      norm1_w + (long)d * HDIM, pHB, nH, nL);
        tcgemm_kernel<E_BIAS><<<ggrid(LTOK, 3 * HDIM), GT, GEMM_SMEM>>>(
            nH, nL, qwH + (long)d * HDIM * 3 * HDIM, qwL + (long)d * HDIM * 3 * HDIM,
            qkv_b + (long)d * 3 * HDIM, nullptr, pQKV, nullptr, nullptr,
            LTOK, 3 * HDIM, HDIM, HDIM, 3 * HDIM, 3 * HDIM);
        attn_kernel<<<NWIN * NHEAD, 256, ATTN_SMEM>>>(pQKV, cosb, sinb, aH, aL);
        tcgemm_kernel<E_BIAS_RES><<<ggrid(LTOK, HDIM), GT, GEMM_SMEM>>>(
            aH, aL, prH + (long)d * HDIM * HDIM, prL + (long)d * HDIM * HDIM,
            proj_b + (long)d * HDIM, pHB, pRES, nullptr, nullptr,
            LTOK, HDIM, HDIM, HDIM, HDIM, HDIM);
        rmsnorm_kernel<<<LTOK, 256>>>(pRES, nullptr, norm2_w + (long)d * HDIM, nullptr, nH, nL);
        // merged gate|up GEMM: N = 6848
        tcgemm_kernel<E_BIAS><<<ggrid(LTOK, GU_N), GT, GEMM_SMEM>>>(
            nH, nL, guH + (long)d * HDIM * GU_N, guL + (long)d * HDIM * GU_N,
            gub + (long)d * GU_N, nullptr, pGU, nullptr, nullptr,
            LTOK, GU_N, HDIM, HDIM, GU_N, GU_N);
        swiglu_kernel<<<LTOK, 256>>>(pGU, sH, sL);
        tcgemm_kernel<E_BIAS><<<ggrid(LTOK, HDIM), GT, GEMM_SMEM>>>(
            sH, sL, dwH + (long)d * MHID * HDIM, dwL + (long)d * MHID * HDIM,
            down_b + (long)d * HDIM, nullptr, pX, nullptr, nullptr,
            LTOK, HDIM, MHID, MH_P, HDIM, HDIM);
    }

    // merger
    rmsnorm_kernel<<<LTOK, 256>>>(pX, pRES, lnq_w, nullptr, nH, nL);
    tcgemm_kernel<E_GELU_SPLIT><<<ggrid(LMERG, H4), GT, GEMM_SMEM>>>(
        nH, nL, m0H, m0L, m0_b, nullptr, nullptr, aH, aL,
        LMERG, H4, H4, H4, H4, H4);
    tcgemm_kernel<E_BIAS><<<ggrid(LMERG, DMODEL), GT, GEMM_SMEM>>>(
        aH, aL, m2H, m2L, m2_b, nullptr, (float*)d_out, nullptr, nullptr,
        LMERG, DMODEL, H4, H4, DMODEL, DMODEL);
}

// round 12
// speedup vs baseline: 2.3513x; 1.0254x over previous
#include <cuda_runtime.h>
#include <cuda_bf16.h>
#include <math.h>
#include <stdint.h>

// ---------------- problem constants ----------------
#define LTOK 8192
#define HDIM 1280
#define NHEAD 16
#define HEADD 80
#define MHID 3420
#define MH_P 3424
#define GU_N 6848
#define NBLK 4
#define NWIN 128
#define PDIM 1176
#define DMODEL 3584
#define H4 5120
#define LMERG 2048

// ---------------- fp32 scratch ----------------
static constexpr long SZ_LH  = (long)LTOK * HDIM;
static constexpr long SZ_L3H = (long)LTOK * 3 * HDIM;

static constexpr long F_X    = 0;
static constexpr long F_RES  = F_X   + SZ_LH;
static constexpr long F_HB   = F_RES + SZ_LH;
static constexpr long F_QKV  = F_HB  + SZ_LH;
static constexpr long F_GU   = F_QKV + SZ_L3H;           // [LTOK][GU_N]
static constexpr long F_TOTAL = F_GU + (long)LTOK * GU_N;
__device__ float g_f32[F_TOTAL];

__device__ float g_bias[NBLK * GU_N];

// ---------------- bf16 scratch (hi/lo pairs) ----------------
static constexpr long SZ_XS  = (long)LTOK * PDIM;
static constexpr long SZ_PW  = (long)PDIM * HDIM;
static constexpr long SZ_QW  = (long)NBLK * HDIM * 3*HDIM;
static constexpr long SZ_PRW = (long)NBLK * HDIM * HDIM;
static constexpr long SZ_GU  = (long)NBLK * HDIM * GU_N;
static constexpr long SZ_DW  = (long)NBLK * MHID * HDIM;
static constexpr long SZ_M0W = (long)H4 * H4;
static constexpr long SZ_M2W = (long)H4 * DMODEL;
static constexpr long SZ_SHP = (long)LTOK * MH_P;

static constexpr long B_XH  = 0;
static constexpr long B_XL  = B_XH + SZ_XS;
static constexpr long B_NH  = B_XL + SZ_XS;
static constexpr long B_NL  = B_NH + SZ_LH;
static constexpr long B_AH  = B_NL + SZ_LH;
static constexpr long B_AL  = B_AH + SZ_LH;
static constexpr long B_SH  = B_AL + SZ_LH;
static constexpr long B_SL  = B_SH + SZ_SHP;
static constexpr long B_PW  = B_SL + SZ_SHP;
static constexpr long B_QW  = B_PW + 2*SZ_PW;
static constexpr long B_PRW = B_QW + 2*SZ_QW;
static constexpr long B_GUH = B_PRW + 2*SZ_PRW;
static constexpr long B_GUL = B_GUH + SZ_GU;
static constexpr long B_DW  = B_GUL + SZ_GU;
static constexpr long B_M0W = B_DW + 2*SZ_DW;
static constexpr long B_M2W = B_M0W + 2*SZ_M0W;
static constexpr long B_TOTAL = B_M2W + 2*SZ_M2W;
__device__ __nv_bfloat16 g_bf16[B_TOTAL];

// ---------------- PTX helpers (base sm_103 target only!) ----------------
__device__ __forceinline__ uint32_t smem_to_u32(const void* p) {
    uint32_t a;
    asm("{ .reg .u64 t; cvta.to.shared.u64 t, %1; cvt.u32.u64 %0, t; }" : "=r"(a) : "l"(p));
    return a;
}
__device__ __forceinline__ void cp16(uint32_t dst, const void* src, int bytes) {
    asm volatile("cp.async.cg.shared.global [%0], [%1], 16, %2;"
                 :: "r"(dst), "l"(src), "r"(bytes));
}
#define CP_COMMIT() asm volatile("cp.async.commit_group;" ::: "memory")
#define CP_WAIT2()  asm volatile("cp.async.wait_group 2;" ::: "memory")

__device__ __forceinline__ void ldsm_x4(uint32_t r[4], uint32_t addr) {
    asm volatile("ldmatrix.sync.aligned.m8n8.x4.shared.b16 {%0,%1,%2,%3}, [%4];"
                 : "=r"(r[0]), "=r"(r[1]), "=r"(r[2]), "=r"(r[3]) : "r"(addr));
}
__device__ __forceinline__ void ldsm_x4t(uint32_t r[4], uint32_t addr) {
    asm volatile("ldmatrix.sync.aligned.m8n8.x4.trans.shared.b16 {%0,%1,%2,%3}, [%4];"
                 : "=r"(r[0]), "=r"(r[1]), "=r"(r[2]), "=r"(r[3]) : "r"(addr));
}
__device__ __forceinline__ void mma_bf16(float c[4], const uint32_t a[4],
                                         uint32_t b0, uint32_t b1) {
    asm volatile(
        "mma.sync.aligned.m16n8k16.row.col.f32.bf16.bf16.f32 "
        "{%0,%1,%2,%3}, {%4,%5,%6,%7}, {%8,%9}, {%0,%1,%2,%3};"
        : "+f"(c[0]), "+f"(c[1]), "+f"(c[2]), "+f"(c[3])
        : "r"(a[0]), "r"(a[1]), "r"(a[2]), "r"(a[3]), "r"(b0), "r"(b1));
}

// ---------------- tensor-core GEMM (bf16x3 split, fp32 accum, optional split-K) ----------------
enum { E_NONE = 0, E_BIAS = 1, E_BIAS_RES = 2, E_GELU_SPLIT = 3 };

#define A_STRIDE 40
#define B_STRIDE 136
#define A_TILE_B (128 * A_STRIDE * 2)      // 10240
#define B_TILE_B (32 * B_STRIDE * 2)       // 8704
#define STAGE_B  (2 * A_TILE_B + 2 * B_TILE_B)  // 37888
#define OFF_AH 0
#define OFF_AL A_TILE_B
#define OFF_BH (2 * A_TILE_B)
#define OFF_BL (2 * A_TILE_B + B_TILE_B)
#define GEMM_SMEM (3 * STAGE_B)            // 113664
#define GT 256

template<int EPI>
__global__ void __launch_bounds__(GT, 2) tcgemm_kernel(
    const __nv_bfloat16* __restrict__ Ah, const __nv_bfloat16* __restrict__ Al,
    const __nv_bfloat16* __restrict__ Bh, const __nv_bfloat16* __restrict__ Bl,
    const float* __restrict__ bias, const float* __restrict__ res,
    float* __restrict__ C, __nv_bfloat16* __restrict__ Oh, __nv_bfloat16* __restrict__ Ol,
    int M, int N, int K, int lda, int ldb, int ldc)
{
    extern __shared__ __align__(16) char sm[];
    const uint32_t smem_u = smem_to_u32(sm);
    const int tid = threadIdx.x;
    const int lane = tid & 31, wid = tid >> 5;
    const int wm = wid >> 2, wn = wid & 3;
    const int row0 = blockIdx.y * 128, col0 = blockIdx.x * 128;

    // split-K chunk range for this z-block
    const int nc_tot = (K + 31) / 32;
    const int S = gridDim.z;
    const int per = (nc_tot + S - 1) / S;
    const int c0 = blockIdx.z * per;
    int c1 = c0 + per; if (c1 > nc_tot) c1 = nc_tot;
    const int myn = (c1 > c0) ? (c1 - c0) : 0;

    auto load_stage = [&](int st, int c) {
        const uint32_t sbase = smem_u + st * STAGE_B;
        const int k0 = c * 32;
        #pragma unroll
        for (int h = 0; h < 2; ++h) {
            const __nv_bfloat16* src = h ? Al : Ah;
            const uint32_t dbase = sbase + (h ? OFF_AL : OFF_AH);
            #pragma unroll
            for (int it = 0; it < 2; ++it) {
                int e = tid + it * 256;
                int r = e >> 2, q = e & 3;
                int gr = row0 + r;
                int gk = k0 + q * 8;
                int bytes = (K - gk) * 2;
                bytes = bytes < 0 ? 0 : (bytes > 16 ? 16 : bytes);
                const __nv_bfloat16* g = src + (long)gr * lda + (bytes > 0 ? gk : 0);
                cp16(dbase + r * (A_STRIDE * 2) + q * 16, g, bytes);
            }
        }
        #pragma unroll
        for (int h = 0; h < 2; ++h) {
            const __nv_bfloat16* src = h ? Bl : Bh;
            const uint32_t dbase = sbase + (h ? OFF_BL : OFF_BH);
            #pragma unroll
            for (int it = 0; it < 2; ++it) {
                int e = tid + it * 256;
                int r = e >> 4, q = e & 15;
                int gk = k0 + r;
                int gc = col0 + q * 8;
                int bytes = (N - gc) * 2;
                bytes = bytes < 0 ? 0 : (bytes > 16 ? 16 : bytes);
                if (gk >= K) bytes = 0;
                const __nv_bfloat16* g = src + (long)(gk < K ? gk : 0) * ldb + (bytes > 0 ? gc : 0);
                cp16(dbase + r * (B_STRIDE * 2) + q * 16, g, bytes);
            }
        }
    };

    const int a_row = lane & 15;
    const int a_kh = (lane >> 4) * 8;
    const int b_g = lane >> 3, b_l = lane & 7;
    const int b_k = (b_g & 1) * 8 + b_l;
    const int b_n = (b_g >> 1) * 8;

    float acc[4][4][4];
    #pragma unroll
    for (int i = 0; i < 4; ++i)
        #pragma unroll
        for (int j = 0; j < 4; ++j)
            #pragma unroll
            for (int r = 0; r < 4; ++r) acc[i][j][r] = 0.f;

    #pragma unroll
    for (int s = 0; s < 3; ++s) {
        if (s < myn) load_stage(s, c0 + s);
        CP_COMMIT();
    }

    for (int cc = 0; cc < myn; ++cc) {
        CP_WAIT2();
        __syncthreads();
        const int st = cc % 3;
        const uint32_t sbase = smem_u + st * STAGE_B;
        const uint32_t aB[2] = { sbase + OFF_AH, sbase + OFF_AL };
        const uint32_t bB[2] = { sbase + OFF_BH, sbase + OFF_BL };

        #pragma unroll
        for (int ks = 0; ks < 2; ++ks) {
            uint32_t af[2][4][4];
            #pragma unroll
            for (int h = 0; h < 2; ++h)
                #pragma unroll
                for (int i = 0; i < 4; ++i)
                    ldsm_x4(af[h][i],
                        aB[h] + 2u * ((wm * 64 + i * 16 + a_row) * A_STRIDE + ks * 16 + a_kh));
            #pragma unroll
            for (int j2 = 0; j2 < 2; ++j2) {
                uint32_t b0[4], b1[4];
                uint32_t boff = 2u * ((ks * 16 + b_k) * B_STRIDE + wn * 32 + j2 * 16 + b_n);
                ldsm_x4t(b0, bB[0] + boff);
                ldsm_x4t(b1, bB[1] + boff);
                #pragma unroll
                for (int i = 0; i < 4; ++i) {
                    mma_bf16(acc[i][2*j2],   af[0][i], b0[0], b0[1]);
                    mma_bf16(acc[i][2*j2+1], af[0][i], b0[2], b0[3]);
                    mma_bf16(acc[i][2*j2],   af[0][i], b1[0], b1[1]);
                    mma_bf16(acc[i][2*j2+1], af[0][i], b1[2], b1[3]);
                    mma_bf16(acc[i][2*j2],   af[1][i], b0[0], b0[1]);
                    mma_bf16(acc[i][2*j2+1], af[1][i], b0[2], b0[3]);
                }
            }
        }
        __syncthreads();
        if (cc + 3 < myn) load_stage(st, c0 + cc + 3);
        CP_COMMIT();
    }

    const bool add_const = (blockIdx.z == 0);
    const int g = lane >> 2, t = lane & 3;
    #pragma unroll
    for (int i = 0; i < 4; ++i) {
        #pragma unroll
        for (int j = 0; j < 4; ++j) {
            int col = col0 + wn * 32 + j * 8 + t * 2;
            if (col >= N) continue;
            float b0 = 0.f, b1 = 0.f;
            if (EPI != E_NONE && add_const) { b0 = bias[col]; b1 = bias[col + 1]; }
            #pragma unroll
            for (int rr = 0; rr < 2; ++rr) {
                int row = row0 + wm * 64 + i * 16 + g + rr * 8;
                if (row >= M) continue;
                float v0 = acc[i][j][rr * 2 + 0] + b0;
                float v1 = acc[i][j][rr * 2 + 1] + b1;
                long idx = (long)row * ldc + col;
                if (EPI == E_BIAS_RES && add_const) { v0 += res[idx]; v1 += res[idx + 1]; }
                if (EPI == E_GELU_SPLIT) {
                    v0 = 0.5f * v0 * (1.f + erff(v0 * 0.70710678118654752f));
                    v1 = 0.5f * v1 * (1.f + erff(v1 * 0.70710678118654752f));
                    __nv_bfloat16 h0 = __float2bfloat16(v0);
                    __nv_bfloat16 h1 = __float2bfloat16(v1);
                    Oh[idx] = h0; Oh[idx + 1] = h1;
                    Ol[idx]     = __float2bfloat16(v0 - __bfloat162float(h0));
                    Ol[idx + 1] = __float2bfloat16(v1 - __bfloat162float(h1));
                } else if (gridDim.z == 1) {
                    *reinterpret_cast<float2*>(C + idx) = make_float2(v0, v1);
                } else {
                    atomicAdd(C + idx, v0);
                    atomicAdd(C + idx + 1, v1);
                }
            }
        }
    }
}

// ---------------- fused windowed attention with inline RoPE (fp32) ----------------
#define SP 81
#define ATTN_SMEM (3 * 64 * SP * 4)

__global__ void __launch_bounds__(256) attn_kernel(
    const float* __restrict__ qkv, const float* __restrict__ cosb,
    const float* __restrict__ sinb, __nv_bfloat16* __restrict__ outH,
    __nv_bfloat16* __restrict__ outL)
{
    extern __shared__ float smf[];
    float* q = smf;
    float* k = smf + 64 * SP;
    float* v = smf + 2 * 64 * SP;
    float* s = smf;                 // aliases q (dead after QK phase)

    const int w = blockIdx.x >> 4;
    const int h = blockIdx.x & 15;
    const int tid = threadIdx.x;
    const float scale = 0.11180339887498949f;

    for (int e = tid; e < 64 * 80; e += 256) {
        int t = e / 80, j = e % 80;
        int l = w * 64 + t;
        long base = (long)l * (3 * HDIM) + h * 80;
        float c = cosb[l * 80 + j], sn = sinb[l * 80 + j];
        float qv = qkv[base + j];
        float qr = (j < 40) ? -qkv[base + j + 40] : qkv[base + j - 40];
        q[t * SP + j] = qv * c + qr * sn;
        float kv = qkv[base + HDIM + j];
        float kr = (j < 40) ? -qkv[base + HDIM + j + 40] : qkv[base + HDIM + j - 40];
        k[t * SP + j] = kv * c + kr * sn;
        v[t * SP + j] = qkv[base + 2 * HDIM + j];
    }
    __syncthreads();

    {
        const int tx = tid & 15, ty = tid >> 4;
        float acc[4][4] = {};
        for (int d = 0; d < 80; d++) {
            float qa[4], kb[4];
            #pragma unroll
            for (int i = 0; i < 4; i++) qa[i] = q[(ty * 4 + i) * SP + d];
            #pragma unroll
            for (int j = 0; j < 4; j++) kb[j] = k[(tx * 4 + j) * SP + d];
            #pragma unroll
            for (int i = 0; i < 4; i++)
                #pragma unroll
                for (int j = 0; j < 4; j++)
                    acc[i][j] += qa[i] * kb[j];
        }
        __syncthreads();
        #pragma unroll
        for (int i = 0; i < 4; i++)
            #pragma unroll
            for (int j = 0; j < 4; j++)
                s[(ty * 4 + i) * 64 + tx * 4 + j] = acc[i][j] * scale;
    }
    __syncthreads();

    {
        const int warp = tid >> 5, lane = tid & 31;
        for (int r = warp; r < 64; r += 8) {
            float x0 = s[r * 64 + lane], x1 = s[r * 64 + 32 + lane];
            float mx = fmaxf(x0, x1);
            #pragma unroll
            for (int o = 16; o > 0; o >>= 1) mx = fmaxf(mx, __shfl_xor_sync(~0u, mx, o));
            float e0 = __expf(x0 - mx), e1 = __expf(x1 - mx);
            float sum = e0 + e1;
            #pragma unroll
            for (int o = 16; o > 0; o >>= 1) sum += __shfl_xor_sync(~0u, sum, o);
            float inv = 1.f / sum;
            s[r * 64 + lane] = e0 * inv;
            s[r * 64 + 32 + lane] = e1 * inv;
        }
    }
    __syncthreads();

    {
        const int tx = tid & 15, ty = tid >> 4;
        float acc[4][5] = {};
        for (int kk = 0; kk < 64; kk++) {
            float sa[4], vb[5];
            #pragma unroll
            for (int i = 0; i < 4; i++) sa[i] = s[(ty * 4 + i) * 64 + kk];
            #pragma unroll
            for (int j = 0; j < 5; j++) vb[j] = v[kk * SP + tx * 5 + j];
            #pragma unroll
            for (int i = 0; i < 4; i++)
                #pragma unroll
                for (int j = 0; j < 5; j++)
                    acc[i][j] += sa[i] * vb[j];
        }
        #pragma unroll
        for (int i = 0; i < 4; i++) {
            long obase = (long)(w * 64 + ty * 4 + i) * HDIM + h * 80 + tx * 5;
            #pragma unroll
            for (int j = 0; j < 5; j++) {
                float val = acc[i][j];
                __nv_bfloat16 hh = __float2bfloat16(val);
                outH[obase + j] = hh;
                outL[obase + j] = __float2bfloat16(val - __bfloat162float(hh));
            }
        }
    }
}

// ---------------- fused (optional add) + RMSNorm, bf16 hi/lo out ----------------
__global__ void __launch_bounds__(256) rmsnorm_kernel(
    const float* __restrict__ a, const float* __restrict__ b,
    const float* __restrict__ w, float* __restrict__ sum_out,
    __nv_bfloat16* __restrict__ nh, __nv_bfloat16* __restrict__ nl)
{
    __shared__ float sv[HDIM];
    __shared__ float red[8];
    __shared__ float s_scale;
    const int row = blockIdx.x, tid = threadIdx.x;
    const long base = (long)row * HDIM;
    float ss = 0.f;
    for (int j = tid; j < HDIM; j += 256) {
        float v = a[base + j];
        if (b) v += b[base + j];
        sv[j] = v;
        if (sum_out) sum_out[base + j] = v;
        ss += v * v;
    }
    #pragma unroll
    for (int o = 16; o > 0; o >>= 1) ss += __shfl_xor_sync(~0u, ss, o);
    if ((tid & 31) == 0) red[tid >> 5] = ss;
    __syncthreads();
    if (tid == 0) {
        float t = 0.f;
        #pragma unroll
        for (int i = 0; i < 8; i++) t += red[i];
        s_scale = rsqrtf(t / (float)HDIM + 1e-6f);
    }
    __syncthreads();
    float sc = s_scale;
    for (int j = tid; j < HDIM; j += 256) {
        float v = sv[j] * sc * w[j];
        __nv_bfloat16 hh = __float2bfloat16(v);
        nh[base + j] = hh;
        nl[base + j] = __float2bfloat16(v - __bfloat162float(hh));
    }
}

// ---------------- SwiGLU over merged [row][GU_N] buffer, bf16 hi/lo out ----------------
__global__ void __launch_bounds__(256) swiglu_kernel(
    const float* __restrict__ gu,
    __nv_bfloat16* __restrict__ oh, __nv_bfloat16* __restrict__ ol)
{
    const int row = blockIdx.x, tid = threadIdx.x;
    const long gbase = (long)row * GU_N;
    const long obase = (long)row * MH_P;
    for (int c = tid * 4; c < MHID; c += 1024) {
        float4 gv = *reinterpret_cast<const float4*>(gu + gbase + c);
        float4 uv = *reinterpret_cast<const float4*>(gu + gbase + MH_P + c);
        float gr[4] = {gv.x, gv.y, gv.z, gv.w};
        float ur[4] = {uv.x, uv.y, uv.z, uv.w};
        __nv_bfloat16 th[4], tl[4];
        #pragma unroll
        for (int j = 0; j < 4; j++) {
            float x = gr[j];
            float v = (c + j < MHID) ? (x / (1.f + __expf(-x)) * ur[j]) : 0.f;
            __nv_bfloat16 hh = __float2bfloat16(v);
            th[j] = hh;
            tl[j] = __float2bfloat16(v - __bfloat162float(hh));
        }
        *reinterpret_cast<uint2*>(oh + obase + c) = *reinterpret_cast<uint2*>(th);
        *reinterpret_cast<uint2*>(ol + obase + c) = *reinterpret_cast<uint2*>(tl);
    }
}

// ---------------- standalone GELU + bf16 hi/lo split (for split-K m0) ----------------
__global__ void __launch_bounds__(256) gelu_split_kernel(
    const float* __restrict__ in, __nv_bfloat16* __restrict__ oh,
    __nv_bfloat16* __restrict__ ol, long n4)
{
    for (long i = (long)blockIdx.x * 256 + threadIdx.x; i < n4; i += (long)gridDim.x * 256) {
        float4 v = *reinterpret_cast<const float4*>(in + 4 * i);
        float vv[4] = {v.x, v.y, v.z, v.w};
        __nv_bfloat16 th[4], tl[4];
        #pragma unroll
        for (int j = 0; j < 4; j++) {
            float x = vv[j];
            float g = 0.5f * x * (1.f + erff(x * 0.70710678118654752f));
            __nv_bfloat16 hh = __float2bfloat16(g);
            th[j] = hh;
            tl[j] = __float2bfloat16(g - __bfloat162float(hh));
        }
        *reinterpret_cast<uint2*>(oh + 4 * i) = *reinterpret_cast<uint2*>(th);
        *reinterpret_cast<uint2*>(ol + 4 * i) = *reinterpret_cast<uint2*>(tl);
    }
}

// ---------------- merged gate|up bias fill ----------------
__global__ void __launch_bounds__(256) fill_bias_kernel(
    const float* __restrict__ gate_b, const float* __restrict__ up_b, float* __restrict__ out)
{
    int i = blockIdx.x * 256 + threadIdx.x;
    if (i >= NBLK * GU_N) return;
    int d = i / GU_N, c = i - d * GU_N;
    float v = 0.f;
    if (c < MHID) v = gate_b[d * MHID + c];
    else if (c >= MH_P && c - MH_P < MHID) v = up_b[d * MHID + (c - MH_P)];
    out[i] = v;
}

// ---------------- fp32 -> bf16 hi/lo splits ----------------
__global__ void __launch_bounds__(256) split_kernel(
    const float4* __restrict__ in, __nv_bfloat16* __restrict__ h,
    __nv_bfloat16* __restrict__ l, long n4)
{
    for (long i = (long)blockIdx.x * 256 + threadIdx.x; i < n4; i += (long)gridDim.x * 256) {
        float4 v = in[i];
        __nv_bfloat16 th[4], tl[4];
        float vv[4] = {v.x, v.y, v.z, v.w};
        #pragma unroll
        for (int j = 0; j < 4; j++) {
            th[j] = __float2bfloat16(vv[j]);
            tl[j] = __float2bfloat16(vv[j] - __bfloat162float(th[j]));
        }
        *reinterpret_cast<uint2*>(h + 4 * i) = *reinterpret_cast<uint2*>(th);
        *reinterpret_cast<uint2*>(l + 4 * i) = *reinterpret_cast<uint2*>(tl);
    }
}

__global__ void __launch_bounds__(256) split_pad_kernel(
    const float* __restrict__ in, __nv_bfloat16* __restrict__ h,
    __nv_bfloat16* __restrict__ l, int rows, int cols, int ldo)
{
    int c4n = cols >> 2;
    long total = (long)rows * c4n;
    for (long i = (long)blockIdx.x * 256 + threadIdx.x; i < total; i += (long)gridDim.x * 256) {
        int r = (int)(i / c4n);
        int c4 = (int)(i - (long)r * c4n);
        float4 v = *reinterpret_cast<const float4*>(in + (long)r * cols + c4 * 4);
        __nv_bfloat16 th[4], tl[4];
        float vv[4] = {v.x, v.y, v.z, v.w};
        #pragma unroll
        for (int j = 0; j < 4; j++) {
            th[j] = __float2bfloat16(vv[j]);
            tl[j] = __float2bfloat16(vv[j] - __bfloat162float(th[j]));
        }
        long o = (long)r * ldo + c4 * 4;
        *reinterpret_cast<uint2*>(h + o) = *reinterpret_cast<uint2*>(th);
        *reinterpret_cast<uint2*>(l + o) = *reinterpret_cast<uint2*>(tl);
    }
}

// ---------------- host ----------------
static inline dim3 ggrid(int M, int N, int S = 1) {
    return dim3((N + 127) / 128, (M + 127) / 128, S);
}

static inline void do_split(const float* src, __nv_bfloat16* h, __nv_bfloat16* l, long n) {
    long n4 = n / 4;
    int blocks = (int)((n4 + 255) / 256);
    if (blocks > 16384) blocks = 16384;
    split_kernel<<<blocks, 256>>>((const float4*)src, h, l, n4);
}
static inline void do_split_pad(const float* src, __nv_bfloat16* h, __nv_bfloat16* l,
                                int rows, int cols, int ldo) {
    long total = (long)rows * (cols / 4);
    int blocks = (int)((total + 255) / 256);
    if (blocks > 16384) blocks = 16384;
    split_pad_kernel<<<blocks, 256>>>(src, h, l, rows, cols, ldo);
}

extern "C" void kernel_launch(void* const* d_in, const int* in_sizes, int n_in,
                              void* d_out, int out_size)
{
    const float* x       = (const float*)d_in[0];
    const float* cosb    = (const float*)d_in[1];
    const float* sinb    = (const float*)d_in[2];
    const float* patch_w = (const float*)d_in[3];
    const float* norm1_w = (const float*)d_in[4];
    const float* norm2_w = (const float*)d_in[5];
    const float* qkv_w   = (const float*)d_in[6];
    const float* qkv_b   = (const float*)d_in[7];
    const float* proj_w  = (const float*)d_in[8];
    const float* proj_b  = (const float*)d_in[9];
    const float* gate_w  = (const float*)d_in[10];
    const float* gate_b  = (const float*)d_in[11];
    const float* up_w    = (const float*)d_in[12];
    const float* up_b    = (const float*)d_in[13];
    const float* down_w  = (const float*)d_in[14];
    const float* down_b  = (const float*)d_in[15];
    const float* lnq_w   = (const float*)d_in[16];
    const float* m0_w    = (const float*)d_in[17];
    const float* m0_b    = (const float*)d_in[18];
    const float* m2_w    = (const float*)d_in[19];
    const float* m2_b    = (const float*)d_in[20];

    float* fs = nullptr;
    __nv_bfloat16* bs = nullptr;
    float* gub = nullptr;
    cudaGetSymbolAddress((void**)&fs, g_f32);
    cudaGetSymbolAddress((void**)&bs, g_bf16);
    cudaGetSymbolAddress((void**)&gub, g_bias);

    float* pX    = fs + F_X;
    float* pRES  = fs + F_RES;
    float* pHB   = fs + F_HB;
    float* pQKV  = fs + F_QKV;
    float* pGU   = fs + F_GU;

    __nv_bfloat16 *xH = bs+B_XH, *xL = bs+B_XL;
    __nv_bfloat16 *nH = bs+B_NH, *nL = bs+B_NL;
    __nv_bfloat16 *aH = bs+B_AH, *aL = bs+B_AL;
    __nv_bfloat16 *sH = bs+B_SH, *sL = bs+B_SL;
    __nv_bfloat16 *pwH = bs+B_PW,  *pwL = pwH + SZ_PW;
    __nv_bfloat16 *qwH = bs+B_QW,  *qwL = qwH + SZ_QW;
    __nv_bfloat16 *prH = bs+B_PRW, *prL = prH + SZ_PRW;
    __nv_bfloat16 *guH = bs+B_GUH, *guL = bs+B_GUL;
    __nv_bfloat16 *dwH = bs+B_DW,  *dwL = dwH + SZ_DW;
    __nv_bfloat16 *m0H = bs+B_M0W, *m0L = m0H + SZ_M0W;
    __nv_bfloat16 *m2H = bs+B_M2W, *m2L = m2H + SZ_M2W;

    cudaFuncSetAttribute(tcgemm_kernel<E_NONE>, cudaFuncAttributeMaxDynamicSharedMemorySize, GEMM_SMEM);
    cudaFuncSetAttribute(tcgemm_kernel<E_BIAS>, cudaFuncAttributeMaxDynamicSharedMemorySize, GEMM_SMEM);
    cudaFuncSetAttribute(tcgemm_kernel<E_BIAS_RES>, cudaFuncAttributeMaxDynamicSharedMemorySize, GEMM_SMEM);
    cudaFuncSetAttribute(attn_kernel, cudaFuncAttributeMaxDynamicSharedMemorySize, ATTN_SMEM);

    do_split(x,       xH,  xL,  SZ_XS);
    do_split(patch_w, pwH, pwL, SZ_PW);
    do_split(qkv_w,   qwH, qwL, SZ_QW);
    do_split(proj_w,  prH, prL, SZ_PRW);
    do_split_pad(gate_w, guH, guL, NBLK * HDIM, MHID, GU_N);

    // patch embed (split-K S=4, atomic)
    cudaMemsetAsync(pX, 0, SZ_LH * sizeof(float));
    tcgemm_kernel<E_NONE><<<ggrid(LTOK, HDIM, 4), GT, GEMM_SMEM>>>(
        xH, xL, pwH, pwL, nullptr, nullptr, pX, nullptr, nullptr,
        LTOK, HDIM, PDIM, PDIM, HDIM, HDIM);

    do_split_pad(up_w, guH + MH_P, guL + MH_P, NBLK * HDIM, MHID, GU_N);
    do_split(down_w,  dwH, dwL, SZ_DW);
    do_split(m0_w,    m0H, m0L, SZ_M0W);
    do_split(m2_w,    m2H, m2L, SZ_M2W);
    fill_bias_kernel<<<(NBLK * GU_N + 255) / 256, 256>>>(gate_b, up_b, gub);

    for (int d = 0; d < NBLK; d++) {
        rmsnorm_kernel<<<LTOK, 256>>>(pX, d == 0 ? nullptr : pRES,
                                      norm1_w + (long)d * HDIM, pHB, nH, nL);
        tcgemm_kernel<E_BIAS><<<ggrid(LTOK, 3 * HDIM), GT, GEMM_SMEM>>>(
            nH, nL, qwH + (long)d * HDIM * 3 * HDIM, qwL + (long)d * HDIM * 3 * HDIM,
            qkv_b + (long)d * 3 * HDIM, nullptr, pQKV, nullptr, nullptr,
            LTOK, 3 * HDIM, HDIM, HDIM, 3 * HDIM, 3 * HDIM);
        attn_kernel<<<NWIN * NHEAD, 256, ATTN_SMEM>>>(pQKV, cosb, sinb, aH, aL);
        // proj + residual (split-K S=4, atomic; bias+res added by z=0)
        cudaMemsetAsync(pRES, 0, SZ_LH * sizeof(float));
        tcgemm_kernel<E_BIAS_RES><<<ggrid(LTOK, HDIM, 4), GT, GEMM_SMEM>>>(
            aH, aL, prH + (long)d * HDIM * HDIM, prL + (long)d * HDIM * HDIM,
            proj_b + (long)d * HDIM, pHB, pRES, nullptr, nullptr,
            LTOK, HDIM, HDIM, HDIM, HDIM, HDIM);
        rmsnorm_kernel<<<LTOK, 256>>>(pRES, nullptr, norm2_w + (long)d * HDIM, nullptr, nH, nL);
        tcgemm_kernel<E_BIAS><<<ggrid(LTOK, GU_N), GT, GEMM_SMEM>>>(
            nH, nL, guH + (long)d * HDIM * GU_N, guL + (long)d * HDIM * GU_N,
            gub + (long)d * GU_N, nullptr, pGU, nullptr, nullptr,
            LTOK, GU_N, HDIM, HDIM, GU_N, GU_N);
        swiglu_kernel<<<LTOK, 256>>>(pGU, sH, sL);
        // down (split-K S=4, atomic)
        cudaMemsetAsync(pX, 0, SZ_LH * sizeof(float));
        tcgemm_kernel<E_BIAS><<<ggrid(LTOK, HDIM, 4), GT, GEMM_SMEM>>>(
            sH, sL, dwH + (long)d * MHID * HDIM, dwL + (long)d * MHID * HDIM,
            down_b + (long)d * HDIM, nullptr, pX, nullptr, nullptr,
            LTOK, HDIM, MHID, MH_P, HDIM, HDIM);
    }

    // merger
    rmsnorm_kernel<<<LTOK, 256>>>(pX, pRES, lnq_w, nullptr, nH, nL);
    // m0 (split-K S=4 into pGU, then standalone gelu+split)
    cudaMemsetAsync(pGU, 0, (long)LMERG * H4 * sizeof(float));
    tcgemm_kernel<E_BIAS><<<ggrid(LMERG, H4, 4), GT, GEMM_SMEM>>>(
        nH, nL, m0H, m0L, m0_b, nullptr, pGU, nullptr, nullptr,
        LMERG, H4, H4, H4, H4, H4);
    gelu_split_kernel<<<16384, 256>>>(pGU, aH, aL, (long)LMERG * H4 / 4);
    // m2 (split-K S=4 into d_out)
    cudaMemsetAsync(d_out, 0, (long)out_size * sizeof(float));
    tcgemm_kernel<E_BIAS><<<ggrid(LMERG, DMODEL, 4), GT, GEMM_SMEM>>>(
        aH, aL, m2H, m2L, m2_b, nullptr, (float*)d_out, nullptr, nullptr,
        LMERG, DMODEL, H4, H4, DMODEL, DMODEL);
}